// round 13
// baseline (speedup 1.0000x reference)
#include <cuda_runtime.h>
#include <cuda_fp16.h>
#include <math.h>
#include <stdint.h>

// ---------------------------------------------------------------------------
// Problem constants
// ---------------------------------------------------------------------------
#define NL 2
#define HH 4
#define CC 512
#define INDIM 256
#define FAN 16
#define NC 47
#define DH 128
#define N0 256
#define N1 4096

// ---------------------------------------------------------------------------
// Device scratch (fp32 + half mirrors)
// ---------------------------------------------------------------------------
__device__ float g_S1E[N1 * CC];
__device__ float g_S1N[N1 * CC];
__device__ float g_S0[N0 * CC];
__device__ float g_AGGC[N1];
__device__ float g_HL[N1 * CC];
__device__ float g_H1[N1 * CC];
__device__ float g_ATT[N1 * CC];
__device__ float g_H2[N1 * CC];

__device__ __half g_S1Eh[N1 * CC];
__device__ __half g_S0h[N0 * CC];
__device__ __half g_AGGFh[N1 * INDIM];
__device__ __half g_AGGh[N1 * CC];
__device__ __half g_H1h[N1 * CC];
__device__ __half g_QKVh[N1 * 3 * CC];
__device__ __half g_ATTOh[N1 * CC];
__device__ __half g_H2h[N1 * CC];
__device__ __half g_FF1h[N1 * 2 * CC];

// half weights
__device__ __half g_embWh[CC * INDIM];
__device__ __half g_sageWh[NL * CC * 2 * CC];
__device__ __half g_qkvWh[NL * 3 * CC * CC];
__device__ __half g_outWh[NL * CC * CC];
__device__ __half g_ffnW1h[NL * 2 * CC * CC];
__device__ __half g_ffnW2h[NL * CC * 2 * CC];
__device__ __half g_clsWh[NC * CC];
__device__ __half g_feats0h[N0 * INDIM];
__device__ __half g_feats1h[N1 * INDIM];

// ---------------------------------------------------------------------------
// helpers
// ---------------------------------------------------------------------------
__device__ __forceinline__ void mma_f16(float* d, const uint32_t* a, const uint32_t* b,
                                        const float* c) {
    asm volatile(
        "mma.sync.aligned.m16n8k16.row.col.f32.f16.f16.f32 "
        "{%0,%1,%2,%3}, {%4,%5,%6,%7}, {%8,%9}, {%10,%11,%12,%13};\n"
        : "=f"(d[0]), "=f"(d[1]), "=f"(d[2]), "=f"(d[3])
        : "r"(a[0]), "r"(a[1]), "r"(a[2]), "r"(a[3]),
          "r"(b[0]), "r"(b[1]),
          "f"(c[0]), "f"(c[1]), "f"(c[2]), "f"(c[3]));
}

__device__ __forceinline__ void ldsm_x4(uint32_t& r0, uint32_t& r1, uint32_t& r2,
                                        uint32_t& r3, uint32_t addr) {
    asm volatile("ldmatrix.sync.aligned.m8n8.x4.shared.b16 {%0,%1,%2,%3}, [%4];"
                 : "=r"(r0), "=r"(r1), "=r"(r2), "=r"(r3) : "r"(addr));
}
__device__ __forceinline__ void ldsm_x4_t(uint32_t& r0, uint32_t& r1, uint32_t& r2,
                                          uint32_t& r3, uint32_t addr) {
    asm volatile("ldmatrix.sync.aligned.m8n8.x4.trans.shared.b16 {%0,%1,%2,%3}, [%4];"
                 : "=r"(r0), "=r"(r1), "=r"(r2), "=r"(r3) : "r"(addr));
}

__device__ __forceinline__ void cpa16(void* smemDst, const void* gsrc, int srcBytes) {
    uint32_t saddr = (uint32_t)__cvta_generic_to_shared(smemDst);
    asm volatile("cp.async.cg.shared.global [%0], [%1], 16, %2;\n"
                 :: "r"(saddr), "l"(gsrc), "r"(srcBytes));
}
__device__ __forceinline__ void cpa_commit() { asm volatile("cp.async.commit_group;\n"); }
__device__ __forceinline__ void cpa_wait2() { asm volatile("cp.async.wait_group 2;\n"); }
__device__ __forceinline__ void cpa_wait1() { asm volatile("cp.async.wait_group 1;\n"); }
__device__ __forceinline__ void cpa_wait0() { asm volatile("cp.async.wait_group 0;\n"); }

__device__ __forceinline__ uint32_t scale_h2(uint32_t u, float s) {
    __half2 hv = *reinterpret_cast<const __half2*>(&u);
    float2 f = __half22float2(hv);
    __half2 o = __floats2half2_rn(f.x * s, f.y * s);
    return *reinterpret_cast<uint32_t*>(&o);
}
__device__ __forceinline__ uint32_t pack_h2(float a, float b) {
    __half2 o = __floats2half2_rn(a, b);
    return *reinterpret_cast<uint32_t*>(&o);
}

// ---------------------------------------------------------------------------
// fp16 cp.async GEMM v4: CTA 128x64x32, 128 thr / 4 warps (2m x 2n),
// warp tile 64x32, ldmatrix frag loads, 4 stages, 3 CTAs/SM.
// C = [A | A2](half) x B^T(half) + epilogue.
// ---------------------------------------------------------------------------
#define GBM 128
#define GBN 64
#define KT 32
#define APH 40                         // halves per smem row (32 + 8 pad) = 80 B
#define STAGES 4
#define STAGE_H ((GBM + GBN) * APH)    // 7680 halves = 15360 B
#define GEMM_SMEM (STAGES * STAGE_H * 2)

__global__ void __launch_bounds__(128, 3) gemm_f16_kernel(
    int M, int N, int K,
    const __half* __restrict__ A, int lda,
    const __half* __restrict__ A2, int kSplit,
    const __half* __restrict__ B, int ldb,
    float* __restrict__ C, __half* __restrict__ Ch, int ldc,
    const float* __restrict__ bias,
    const float* __restrict__ biasScale,
    int relu,
    const float* __restrict__ addC,
    const float* __restrict__ rowMask)
{
    extern __shared__ __half smh[];

    const int bm = blockIdx.y * GBM;
    const int bn = blockIdx.x * GBN;
    const int t = threadIdx.x;
    const int lane = t & 31;
    const int wid = t >> 5;          // 0..3
    const int q = lane >> 2;
    const int r = lane & 3;
    const int grp = lane >> 3;       // 0..3
    const int lr = lane & 7;
    const int wm = (wid & 1) * 64;   // 2 warps in M
    const int wn = (wid >> 1) * 32;  // 2 warps in N

    float acc[4][4][4];
    #pragma unroll
    for (int mi = 0; mi < 4; mi++)
        #pragma unroll
        for (int ni = 0; ni < 4; ni++)
            #pragma unroll
            for (int e = 0; e < 4; e++) acc[mi][ni][e] = 0.0f;

    auto issueStage = [&](int buf, int k0) {
        __half* sA = smh + buf * STAGE_H;
        __half* sB = sA + GBM * APH;
        const __half* Asrc = (k0 < kSplit) ? A : A2;
        const int kk = (k0 < kSplit) ? k0 : (k0 - kSplit);
        #pragma unroll
        for (int i = 0; i < 4; i++) {
            int idx = t + 128 * i;
            int row = idx >> 2;
            int c8 = (idx & 3) * 8;
            int gm = bm + row;
            int ok = (gm < M);
            cpa16(sA + row * APH + c8,
                  Asrc + (long long)(ok ? gm : 0) * lda + kk + c8, ok ? 16 : 0);
        }
        #pragma unroll
        for (int i = 0; i < 2; i++) {
            int idx = t + 128 * i;
            int row = idx >> 2;
            int c8 = (idx & 3) * 8;
            int gn = bn + row;
            int ok = (gn < N);
            cpa16(sB + row * APH + c8,
                  B + (long long)(ok ? gn : 0) * ldb + k0 + c8, ok ? 16 : 0);
        }
    };

    auto computeStage = [&](int buf) {
        const uint32_t sa = (uint32_t)__cvta_generic_to_shared(smh + buf * STAGE_H);
        const uint32_t sb = (uint32_t)__cvta_generic_to_shared(smh + buf * STAGE_H + GBM * APH);
        #pragma unroll
        for (int ks = 0; ks < 2; ks++) {
            const int kb = ks * 16;
            uint32_t af[4][4], bf[4][2];
            // A-frags: m16k16; grp&1 -> +8 rows, grp&2 -> +8 cols (validated)
            #pragma unroll
            for (int mi = 0; mi < 4; mi++) {
                int arow = wm + mi * 16 + ((grp & 1) ? 8 : 0) + lr;
                int acol = kb + ((grp & 2) ? 8 : 0);
                ldsm_x4(af[mi][0], af[mi][1], af[mi][2], af[mi][3],
                        sa + (arow * APH + acol) * 2);
            }
            // B-frags: two n8 groups per ldsm; grp&2 -> +8 rows(n), grp&1 -> +8 cols(k)
            #pragma unroll
            for (int nfp = 0; nfp < 2; nfp++) {
                int brow = wn + nfp * 16 + ((grp & 2) ? 8 : 0) + lr;
                int bcol = kb + ((grp & 1) ? 8 : 0);
                uint32_t b0, b1, b2, b3;
                ldsm_x4(b0, b1, b2, b3, sb + (brow * APH + bcol) * 2);
                bf[2 * nfp][0] = b0;      bf[2 * nfp][1] = b1;
                bf[2 * nfp + 1][0] = b2;  bf[2 * nfp + 1][1] = b3;
            }
            #pragma unroll
            for (int mi = 0; mi < 4; mi++)
                #pragma unroll
                for (int ni = 0; ni < 4; ni++)
                    mma_f16(acc[mi][ni], af[mi], bf[ni], acc[mi][ni]);
        }
    };

    const int ntiles = K / KT;
    #pragma unroll
    for (int s = 0; s < STAGES - 1; s++) {
        if (s < ntiles) issueStage(s, s * KT);
        cpa_commit();
    }
    for (int it = 0; it < ntiles; it++) {
        cpa_wait2();
        __syncthreads();
        const int nj = it + STAGES - 1;
        if (nj < ntiles) issueStage(nj & (STAGES - 1), nj * KT);
        cpa_commit();
        computeStage(it & (STAGES - 1));
    }

    // ---- epilogue ----
    #pragma unroll
    for (int mi = 0; mi < 4; mi++) {
        #pragma unroll
        for (int hh = 0; hh < 2; hh++) {
            int gm = bm + wm + mi * 16 + q + hh * 8;
            if (gm >= M) continue;
            float bs = biasScale ? biasScale[gm] : 1.0f;
            float rmv = rowMask ? rowMask[gm] : 1.0f;
            #pragma unroll
            for (int ni = 0; ni < 4; ni++) {
                int gn0 = bn + wn + ni * 8 + 2 * r;
                if (gn0 >= N) continue;
                float v[2];
                #pragma unroll
                for (int j = 0; j < 2; j++) {
                    int gn = gn0 + j;
                    float x = acc[mi][ni][hh * 2 + j];
                    if (bias && gn < N) x += bias[gn] * bs;
                    if (relu) x = fmaxf(x, 0.0f);
                    if (addC && gn < N) x += addC[(long long)gm * ldc + gn];
                    v[j] = x * rmv;
                }
                if (C) {
                    C[(long long)gm * ldc + gn0] = v[0];
                    if (gn0 + 1 < N) C[(long long)gm * ldc + gn0 + 1] = v[1];
                }
                if (Ch) {
                    *reinterpret_cast<__half2*>(Ch + (long long)gm * ldc + gn0) =
                        __floats2half2_rn(v[0], v[1]);
                }
            }
        }
    }
}

// ---------------------------------------------------------------------------
// fp16 flash attention, double-buffered K/V (R12-proven).
// CTA = 64 query rows x 1 head, 128 thr / 4 warps; KV tiles of 64.
// ---------------------------------------------------------------------------
#define FPITCH_H 136
#define FL_STAGE_H (2 * 64 * FPITCH_H)
#define FLASH_SMEM (2 * FL_STAGE_H * 2)

__global__ void __launch_bounds__(128) flash_f16_kernel(
    const __half* __restrict__ QKV, __half* __restrict__ O, int n)
{
    extern __shared__ __half fsm[];

    const int t = threadIdx.x;
    const int warp = t >> 5;
    const int lane = t & 31;
    const int q = lane >> 2;
    const int r = lane & 3;
    const int head = blockIdx.y;
    const int qbase = blockIdx.x * 64;
    const int row0 = warp * 16 + q;
    const float scale = 0.08838834764831845f;

    const uint32_t sbase = (uint32_t)__cvta_generic_to_shared(fsm);

    auto issueKV = [&](int kt, int buf) {
        __half* sK = fsm + buf * FL_STAGE_H;
        __half* sV = sK + 64 * FPITCH_H;
        #pragma unroll
        for (int i = 0; i < 8; i++) {
            int idx = t + 128 * i;
            int row = idx >> 4;
            int c8 = (idx & 15) * 8;
            const __half* kp = QKV + (long long)(kt * 64 + row) * (3 * CC) + CC + head * DH + c8;
            cpa16(sK + row * FPITCH_H + c8, kp, 16);
            cpa16(sV + row * FPITCH_H + c8, kp + CC, 16);
        }
    };

    uint32_t qf[8][4];
    {
        const __half* q0p = QKV + (long long)(qbase + row0) * (3 * CC) + head * DH;
        const __half* q1p = q0p + 8LL * (3 * CC);
        #pragma unroll
        for (int kc = 0; kc < 8; kc++) {
            qf[kc][0] = scale_h2(*(const uint32_t*)(q0p + kc * 16 + 2 * r), scale);
            qf[kc][1] = scale_h2(*(const uint32_t*)(q1p + kc * 16 + 2 * r), scale);
            qf[kc][2] = scale_h2(*(const uint32_t*)(q0p + kc * 16 + 2 * r + 8), scale);
            qf[kc][3] = scale_h2(*(const uint32_t*)(q1p + kc * 16 + 2 * r + 8), scale);
        }
    }

    float oacc[16][4];
    #pragma unroll
    for (int df = 0; df < 16; df++)
        #pragma unroll
        for (int e = 0; e < 4; e++) oacc[df][e] = 0.0f;
    float m0 = -1e30f, m1 = -1e30f, l0 = 0.0f, l1 = 0.0f;

    const int grp = lane >> 3;
    const int lr = lane & 7;

    const int ntiles = n / 64;
    issueKV(0, 0);
    cpa_commit();

    for (int kt = 0; kt < ntiles; kt++) {
        if (kt + 1 < ntiles) {
            issueKV(kt + 1, (kt + 1) & 1);
            cpa_commit();
            cpa_wait1();
        } else {
            cpa_wait0();
        }
        __syncthreads();

        const uint32_t skb = sbase + ((kt & 1) * FL_STAGE_H) * 2;
        const uint32_t svb = skb + 64 * FPITCH_H * 2;

        float sacc[8][4];
        #pragma unroll
        for (int nf = 0; nf < 8; nf++)
            #pragma unroll
            for (int e = 0; e < 4; e++) sacc[nf][e] = 0.0f;
        #pragma unroll
        for (int kc = 0; kc < 8; kc++) {
            #pragma unroll
            for (int nfp = 0; nfp < 4; nfp++) {
                int kvr = nfp * 16 + ((grp & 2) ? 8 : 0) + lr;
                int dc = kc * 16 + ((grp & 1) ? 8 : 0);
                uint32_t b0, b1, b2, b3;
                ldsm_x4(b0, b1, b2, b3, skb + (kvr * FPITCH_H + dc) * 2);
                uint32_t bA[2] = {b0, b1}, bB[2] = {b2, b3};
                mma_f16(sacc[2 * nfp], qf[kc], bA, sacc[2 * nfp]);
                mma_f16(sacc[2 * nfp + 1], qf[kc], bB, sacc[2 * nfp + 1]);
            }
        }

        float tm0 = -1e30f, tm1 = -1e30f;
        #pragma unroll
        for (int nf = 0; nf < 8; nf++) {
            tm0 = fmaxf(tm0, fmaxf(sacc[nf][0], sacc[nf][1]));
            tm1 = fmaxf(tm1, fmaxf(sacc[nf][2], sacc[nf][3]));
        }
        tm0 = fmaxf(tm0, __shfl_xor_sync(0xffffffffu, tm0, 1));
        tm0 = fmaxf(tm0, __shfl_xor_sync(0xffffffffu, tm0, 2));
        tm1 = fmaxf(tm1, __shfl_xor_sync(0xffffffffu, tm1, 1));
        tm1 = fmaxf(tm1, __shfl_xor_sync(0xffffffffu, tm1, 2));
        const float nm0 = fmaxf(m0, tm0);
        const float nm1 = fmaxf(m1, tm1);
        const float cor0 = __expf(m0 - nm0);
        const float cor1 = __expf(m1 - nm1);
        m0 = nm0; m1 = nm1;

        float ts0 = 0.0f, ts1 = 0.0f;
        #pragma unroll
        for (int nf = 0; nf < 8; nf++) {
            sacc[nf][0] = __expf(sacc[nf][0] - m0);
            sacc[nf][1] = __expf(sacc[nf][1] - m0);
            sacc[nf][2] = __expf(sacc[nf][2] - m1);
            sacc[nf][3] = __expf(sacc[nf][3] - m1);
            ts0 += sacc[nf][0] + sacc[nf][1];
            ts1 += sacc[nf][2] + sacc[nf][3];
        }
        ts0 += __shfl_xor_sync(0xffffffffu, ts0, 1);
        ts0 += __shfl_xor_sync(0xffffffffu, ts0, 2);
        ts1 += __shfl_xor_sync(0xffffffffu, ts1, 1);
        ts1 += __shfl_xor_sync(0xffffffffu, ts1, 2);
        l0 = l0 * cor0 + ts0;
        l1 = l1 * cor1 + ts1;

        uint32_t pf[4][4];
        #pragma unroll
        for (int j = 0; j < 4; j++) {
            pf[j][0] = pack_h2(sacc[2 * j][0], sacc[2 * j][1]);
            pf[j][1] = pack_h2(sacc[2 * j][2], sacc[2 * j][3]);
            pf[j][2] = pack_h2(sacc[2 * j + 1][0], sacc[2 * j + 1][1]);
            pf[j][3] = pack_h2(sacc[2 * j + 1][2], sacc[2 * j + 1][3]);
        }

        #pragma unroll
        for (int df = 0; df < 16; df++) {
            oacc[df][0] *= cor0; oacc[df][1] *= cor0;
            oacc[df][2] *= cor1; oacc[df][3] *= cor1;
        }

        #pragma unroll
        for (int j = 0; j < 4; j++) {
            #pragma unroll
            for (int dfp = 0; dfp < 8; dfp++) {
                int kvr = 16 * j + ((grp & 1) ? 8 : 0) + lr;
                int dc = dfp * 16 + ((grp & 2) ? 8 : 0);
                uint32_t b0, b1, b2, b3;
                ldsm_x4_t(b0, b1, b2, b3, svb + (kvr * FPITCH_H + dc) * 2);
                uint32_t bA[2] = {b0, b1}, bB[2] = {b2, b3};
                mma_f16(oacc[2 * dfp], pf[j], bA, oacc[2 * dfp]);
                mma_f16(oacc[2 * dfp + 1], pf[j], bB, oacc[2 * dfp + 1]);
            }
        }
        __syncthreads();
    }

    const float inv0 = 1.0f / l0;
    const float inv1 = 1.0f / l1;
    #pragma unroll
    for (int df = 0; df < 16; df++) {
        const int gc = head * DH + df * 8 + 2 * r;
        *reinterpret_cast<__half2*>(O + (long long)(qbase + row0) * CC + gc) =
            __floats2half2_rn(oacc[df][0] * inv0, oacc[df][1] * inv0);
        *reinterpret_cast<__half2*>(O + (long long)(qbase + row0 + 8) * CC + gc) =
            __floats2half2_rn(oacc[df][2] * inv1, oacc[df][3] * inv1);
    }
}

// ---------------------------------------------------------------------------
// Block reduction
// ---------------------------------------------------------------------------
__device__ __forceinline__ float blockReduceSum(float v, float* red) {
    #pragma unroll
    for (int o = 16; o > 0; o >>= 1) v += __shfl_xor_sync(0xffffffffu, v, o);
    int w = threadIdx.x >> 5;
    if ((threadIdx.x & 31) == 0) red[w] = v;
    __syncthreads();
    float rr;
    if (threadIdx.x < 32) {
        rr = (threadIdx.x < (blockDim.x >> 5)) ? red[threadIdx.x] : 0.0f;
        #pragma unroll
        for (int o = 16; o > 0; o >>= 1) rr += __shfl_xor_sync(0xffffffffu, rr, o);
        if (threadIdx.x == 0) red[0] = rr;
    }
    __syncthreads();
    rr = red[0];
    __syncthreads();
    return rr;
}

// ---------------------------------------------------------------------------
// LN(a+b)*g+beta -> fp32 out + half out
// ---------------------------------------------------------------------------
__global__ void add_ln_kernel(const float* __restrict__ a, const float* __restrict__ b,
                              const float* __restrict__ g, const float* __restrict__ be,
                              float* __restrict__ out, __half* __restrict__ outH)
{
    long long row = blockIdx.x;
    const float* ar = a + row * CC;
    const float* br = b + row * CC;
    int tid = threadIdx.x;
    float x0 = ar[tid] + br[tid];
    float x1 = ar[tid + 256] + br[tid + 256];
    __shared__ float red[8];
    float mu = blockReduceSum(x0 + x1, red) * (1.0f / CC);
    float d0 = x0 - mu, d1 = x1 - mu;
    float var = blockReduceSum(d0 * d0 + d1 * d1, red) * (1.0f / CC);
    float rstd = rsqrtf(var + 1e-5f);
    float y0 = d0 * rstd * g[tid] + be[tid];
    float y1 = d1 * rstd * g[tid + 256] + be[tid + 256];
    out[row * CC + tid] = y0;
    out[row * CC + tid + 256] = y1;
    outH[row * CC + tid] = __float2half(y0);
    outH[row * CC + tid + 256] = __float2half(y1);
}

// ---------------------------------------------------------------------------
// Masked-mean aggregation, vectorized float4 -> half2 out (+ optional coef)
// ---------------------------------------------------------------------------
__global__ void agg_kernel(const float* __restrict__ X, int C,
                           const int* __restrict__ nbm,
                           const float* __restrict__ childMask,
                           __half* __restrict__ out, float* __restrict__ coefOut, int P)
{
    int C4 = C >> 2;
    long long idx = (long long)blockIdx.x * blockDim.x + threadIdx.x;
    if (idx >= (long long)P * C4) return;
    int p = (int)(idx / C4);
    int c4 = (int)(idx % C4);
    const float4* X4 = (const float4*)X;
    float4 sum = make_float4(0.f, 0.f, 0.f, 0.f);
    float den = 0.0f, wsum = 0.0f;
    #pragma unroll
    for (int f = 0; f < FAN; f++) {
        float nb = (float)nbm[p * FAN + f];
        den += nb;
        float w = nb * (childMask ? childMask[p * FAN + f] : 1.0f);
        wsum += w;
        float4 v = X4[(long long)(p * FAN + f) * C4 + c4];
        sum.x += w * v.x; sum.y += w * v.y; sum.z += w * v.z; sum.w += w * v.w;
    }
    den = fmaxf(den, 1.0f);
    float inv = 1.0f / den;
    __half2 a = __floats2half2_rn(sum.x * inv, sum.y * inv);
    __half2 b = __floats2half2_rn(sum.z * inv, sum.w * inv);
    uint2 o;
    o.x = *reinterpret_cast<uint32_t*>(&a);
    o.y = *reinterpret_cast<uint32_t*>(&b);
    ((uint2*)out)[(long long)p * C4 + c4] = o;
    if (coefOut && c4 == 0) coefOut[p] = wsum * inv;
}

// ---------------------------------------------------------------------------
// Multi-segment vectorized fp32 -> fp16 conversion
// ---------------------------------------------------------------------------
#define MAXSEG 12
struct CvtJobs {
    const float* src[MAXSEG];
    __half* dst[MAXSEG];
    int quads[MAXSEG];
    int nseg;
};

__global__ void cvt_multi_kernel(CvtJobs jobs)
{
    int seg = blockIdx.y;
    if (seg >= jobs.nseg) return;
    const float4* src = (const float4*)jobs.src[seg];
    uint2* dst = (uint2*)jobs.dst[seg];
    int nq = jobs.quads[seg];
    for (int i = blockIdx.x * blockDim.x + threadIdx.x; i < nq; i += gridDim.x * blockDim.x) {
        float4 v = src[i];
        __half2 a = __floats2half2_rn(v.x, v.y);
        __half2 b = __floats2half2_rn(v.z, v.w);
        uint2 o;
        o.x = *reinterpret_cast<uint32_t*>(&a);
        o.y = *reinterpret_cast<uint32_t*>(&b);
        dst[i] = o;
    }
}

// ---------------------------------------------------------------------------
// Host orchestration
// ---------------------------------------------------------------------------
static void gemm(int M, int N, int K,
                 const __half* A, int lda, const __half* A2, int kSplit,
                 const __half* B, int ldb,
                 float* C, __half* Ch, int ldc,
                 const float* bias, const float* biasScale, int relu,
                 const float* addC, const float* rowMask)
{
    dim3 grid((N + GBN - 1) / GBN, (M + GBM - 1) / GBM);
    gemm_f16_kernel<<<grid, 128, GEMM_SMEM>>>(
        M, N, K, A, lda, A2, kSplit, B, ldb, C, Ch, ldc,
        bias, biasScale, relu, addC, rowMask);
}

struct Scratch {
    float *S1E, *S1N, *S0, *AGGC, *HL, *H1, *ATT, *H2;
    __half *S1Eh, *S0h, *AGGFh, *AGGh, *H1h, *QKVh, *ATTOh, *H2h, *FF1h;
    __half *embWh, *sageWh, *qkvWh, *outWh, *ffnW1h, *ffnW2h, *clsWh, *feats0h, *feats1h;
};

static Scratch get_scratch() {
    Scratch s; void* p;
    cudaGetSymbolAddress(&p, g_S1E);    s.S1E    = (float*)p;
    cudaGetSymbolAddress(&p, g_S1N);    s.S1N    = (float*)p;
    cudaGetSymbolAddress(&p, g_S0);     s.S0     = (float*)p;
    cudaGetSymbolAddress(&p, g_AGGC);   s.AGGC   = (float*)p;
    cudaGetSymbolAddress(&p, g_HL);     s.HL     = (float*)p;
    cudaGetSymbolAddress(&p, g_H1);     s.H1     = (float*)p;
    cudaGetSymbolAddress(&p, g_ATT);    s.ATT    = (float*)p;
    cudaGetSymbolAddress(&p, g_H2);     s.H2     = (float*)p;
    cudaGetSymbolAddress(&p, g_S1Eh);   s.S1Eh   = (__half*)p;
    cudaGetSymbolAddress(&p, g_S0h);    s.S0h    = (__half*)p;
    cudaGetSymbolAddress(&p, g_AGGFh);  s.AGGFh  = (__half*)p;
    cudaGetSymbolAddress(&p, g_AGGh);   s.AGGh   = (__half*)p;
    cudaGetSymbolAddress(&p, g_H1h);    s.H1h    = (__half*)p;
    cudaGetSymbolAddress(&p, g_QKVh);   s.QKVh   = (__half*)p;
    cudaGetSymbolAddress(&p, g_ATTOh);  s.ATTOh  = (__half*)p;
    cudaGetSymbolAddress(&p, g_H2h);    s.H2h    = (__half*)p;
    cudaGetSymbolAddress(&p, g_FF1h);   s.FF1h   = (__half*)p;
    cudaGetSymbolAddress(&p, g_embWh);  s.embWh  = (__half*)p;
    cudaGetSymbolAddress(&p, g_sageWh); s.sageWh = (__half*)p;
    cudaGetSymbolAddress(&p, g_qkvWh);  s.qkvWh  = (__half*)p;
    cudaGetSymbolAddress(&p, g_outWh);  s.outWh  = (__half*)p;
    cudaGetSymbolAddress(&p, g_ffnW1h); s.ffnW1h = (__half*)p;
    cudaGetSymbolAddress(&p, g_ffnW2h); s.ffnW2h = (__half*)p;
    cudaGetSymbolAddress(&p, g_clsWh);  s.clsWh  = (__half*)p;
    cudaGetSymbolAddress(&p, g_feats0h); s.feats0h = (__half*)p;
    cudaGetSymbolAddress(&p, g_feats1h); s.feats1h = (__half*)p;
    return s;
}

struct LayerW {
    const __half *sageW, *qkvW, *outW, *ffnW1, *ffnW2;
    const float *sageB, *qkvB, *outB, *ffnB1, *ffnB2;
    const float *n1g, *n1b, *n2g, *n2b;
};

static void block_forward(int n, const float* sf, const __half* sfh, const __half* agg,
                          float* outState, __half* outStateH,
                          const float* rowMask, const LayerW& w, const Scratch& s)
{
    gemm(n, CC, 2 * CC, sfh, CC, agg, CC, w.sageW, 2 * CC,
         s.HL, nullptr, CC, w.sageB, nullptr, 0, nullptr, nullptr);
    add_ln_kernel<<<n, 256>>>(sf, s.HL, w.n1g, w.n1b, s.H1, s.H1h);

    gemm(n, 3 * CC, CC, s.H1h, CC, nullptr, CC, w.qkvW, CC,
         nullptr, s.QKVh, 3 * CC, w.qkvB, nullptr, 0, nullptr, nullptr);

    {
        dim3 grid(n / 64, HH);
        flash_f16_kernel<<<grid, 128, FLASH_SMEM>>>(s.QKVh, s.ATTOh, n);
    }

    gemm(n, CC, CC, s.ATTOh, CC, nullptr, CC, w.outW, CC,
         s.ATT, nullptr, CC, w.outB, nullptr, 0, nullptr, nullptr);
    add_ln_kernel<<<n, 256>>>(s.H1, s.ATT, w.n2g, w.n2b, s.H2, s.H2h);

    gemm(n, 2 * CC, CC, s.H2h, CC, nullptr, CC, w.ffnW1, CC,
         nullptr, s.FF1h, 2 * CC, w.ffnB1, nullptr, 1, nullptr, nullptr);
    gemm(n, CC, 2 * CC, s.FF1h, 2 * CC, nullptr, 2 * CC, w.ffnW2, 2 * CC,
         outState, outStateH, CC, w.ffnB2, nullptr, 0, s.H2, rowMask);
}

extern "C" void kernel_launch(void* const* d_in, const int* in_sizes, int n_in,
                              void* d_out, int out_size)
{
    const float* feats0  = (const float*)d_in[0];
    const float* feats1  = (const float*)d_in[1];
    const float* feats2  = (const float*)d_in[2];
    const float* nmask0  = (const float*)d_in[3];
    const float* nmask1  = (const float*)d_in[4];
    const float* nmask2  = (const float*)d_in[5];
    const int*   nbmask0 = (const int*)d_in[6];
    const int*   nbmask1 = (const int*)d_in[7];
    const float* emb_w   = (const float*)d_in[8];
    const float* emb_b   = (const float*)d_in[9];
    const float* sage_w  = (const float*)d_in[10];
    const float* sage_b  = (const float*)d_in[11];
    const float* qkv_w   = (const float*)d_in[12];
    const float* qkv_b   = (const float*)d_in[13];
    const float* out_w   = (const float*)d_in[14];
    const float* out_b   = (const float*)d_in[15];
    const float* n1_g    = (const float*)d_in[16];
    const float* n1_b    = (const float*)d_in[17];
    const float* n2_g    = (const float*)d_in[18];
    const float* n2_b    = (const float*)d_in[19];
    const float* ffn_w1  = (const float*)d_in[20];
    const float* ffn_b1  = (const float*)d_in[21];
    const float* ffn_w2  = (const float*)d_in[22];
    const float* ffn_b2  = (const float*)d_in[23];
    const float* cls_w   = (const float*)d_in[24];
    const float* cls_b   = (const float*)d_in[25];
    float* out = (float*)d_out;

    cudaFuncSetAttribute(gemm_f16_kernel, cudaFuncAttributeMaxDynamicSharedMemorySize,
                         GEMM_SMEM);
    cudaFuncSetAttribute(flash_f16_kernel, cudaFuncAttributeMaxDynamicSharedMemorySize,
                         FLASH_SMEM);

    Scratch s = get_scratch();

    // ---- all fp32->fp16 conversions in one vectorized launch ----
    {
        CvtJobs j;
        j.src[0] = emb_w;   j.dst[0] = s.embWh;   j.quads[0] = CC * INDIM / 4;
        j.src[1] = sage_w;  j.dst[1] = s.sageWh;  j.quads[1] = NL * CC * 2 * CC / 4;
        j.src[2] = qkv_w;   j.dst[2] = s.qkvWh;   j.quads[2] = NL * 3 * CC * CC / 4;
        j.src[3] = out_w;   j.dst[3] = s.outWh;   j.quads[3] = NL * CC * CC / 4;
        j.src[4] = ffn_w1;  j.dst[4] = s.ffnW1h;  j.quads[4] = NL * 2 * CC * CC / 4;
        j.src[5] = ffn_w2;  j.dst[5] = s.ffnW2h;  j.quads[5] = NL * CC * 2 * CC / 4;
        j.src[6] = cls_w;   j.dst[6] = s.clsWh;   j.quads[6] = NC * CC / 4;
        j.src[7] = feats0;  j.dst[7] = s.feats0h; j.quads[7] = N0 * INDIM / 4;
        j.src[8] = feats1;  j.dst[8] = s.feats1h; j.quads[8] = N1 * INDIM / 4;
        j.nseg = 9;
        for (int i = j.nseg; i < MAXSEG; i++) { j.src[i] = nullptr; j.dst[i] = nullptr; j.quads[i] = 0; }
        dim3 grid(128, j.nseg);
        cvt_multi_kernel<<<grid, 256>>>(j);
    }

    LayerW w[NL];
    for (int li = 0; li < NL; li++) {
        w[li].sageW = s.sageWh + (long long)li * CC * 2 * CC;
        w[li].qkvW  = s.qkvWh  + (long long)li * 3 * CC * CC;
        w[li].outW  = s.outWh  + (long long)li * CC * CC;
        w[li].ffnW1 = s.ffnW1h + (long long)li * 2 * CC * CC;
        w[li].ffnW2 = s.ffnW2h + (long long)li * CC * 2 * CC;
        w[li].sageB = sage_b + li * CC;
        w[li].qkvB  = qkv_b  + li * 3 * CC;
        w[li].outB  = out_b  + li * CC;
        w[li].ffnB1 = ffn_b1 + li * 2 * CC;
        w[li].ffnB2 = ffn_b2 + li * CC;
        w[li].n1g = n1_g + li * CC;  w[li].n1b = n1_b + li * CC;
        w[li].n2g = n2_g + li * CC;  w[li].n2b = n2_b + li * CC;
    }

    // ---- embeddings (depth 0, 1), masked; write fp32 + half ----
    gemm(N0, CC, INDIM, s.feats0h, INDIM, nullptr, INDIM, s.embWh, INDIM,
         s.S0, s.S0h, CC, emb_b, nullptr, 0, nullptr, nmask0);
    gemm(N1, CC, INDIM, s.feats1h, INDIM, nullptr, INDIM, s.embWh, INDIM,
         s.S1E, s.S1Eh, CC, emb_b, nullptr, 0, nullptr, nmask1);

    // ---- depth-2: aggregate RAW feats2 then one embedding GEMM ----
    agg_kernel<<<(int)(((long long)N1 * INDIM / 4 + 255) / 256), 256>>>(
        feats2, INDIM, nbmask1, nmask2, s.AGGFh, s.AGGC, N1);
    gemm(N1, CC, INDIM, s.AGGFh, INDIM, nullptr, INDIM, s.embWh, INDIM,
         nullptr, s.AGGh, CC, emb_b, s.AGGC, 0, nullptr, nullptr);

    // ---- layer 0, depth 1 (n=4096) ----
    block_forward(N1, s.S1E, s.S1Eh, s.AGGh, s.S1N, nullptr, nmask1, w[0], s);

    // ---- layer 0, depth 0 ----
    agg_kernel<<<(int)(((long long)N0 * CC / 4 + 255) / 256), 256>>>(
        s.S1E, CC, nbmask0, nullptr, s.AGGh, nullptr, N0);
    block_forward(N0, s.S0, s.S0h, s.AGGh, s.S0, s.S0h, nmask0, w[0], s);

    // ---- layer 1, depth 0 ----
    agg_kernel<<<(int)(((long long)N0 * CC / 4 + 255) / 256), 256>>>(
        s.S1N, CC, nbmask0, nullptr, s.AGGh, nullptr, N0);
    block_forward(N0, s.S0, s.S0h, s.AGGh, s.S0, s.S0h, nmask0, w[1], s);

    // ---- classifier ----
    gemm(N0, NC, CC, s.S0h, CC, nullptr, CC, s.clsWh, CC,
         out, nullptr, NC, cls_b, nullptr, 0, nullptr, nullptr);
}

// round 14
// speedup vs baseline: 1.1094x; 1.1094x over previous
#include <cuda_runtime.h>
#include <cuda_fp16.h>
#include <math.h>
#include <stdint.h>

// ---------------------------------------------------------------------------
// Problem constants
// ---------------------------------------------------------------------------
#define NL 2
#define HH 4
#define CC 512
#define INDIM 256
#define FAN 16
#define NC 47
#define DH 128
#define N0 256
#define N1 4096

// ---------------------------------------------------------------------------
// Device scratch (fp32 + half mirrors)
// ---------------------------------------------------------------------------
__device__ float g_S1E[N1 * CC];
__device__ float g_S1N[N1 * CC];
__device__ float g_S0[N0 * CC];
__device__ float g_AGGC[N1];
__device__ float g_HL[N1 * CC];
__device__ float g_H1[N1 * CC];
__device__ float g_ATT[N1 * CC];
__device__ float g_H2[N1 * CC];

__device__ __half g_S1Eh[N1 * CC];
__device__ __half g_S0h[N0 * CC];
__device__ __half g_AGGFh[N1 * INDIM];
__device__ __half g_AGGh[N1 * CC];
__device__ __half g_H1h[N1 * CC];
__device__ __half g_QKVh[N1 * 3 * CC];
__device__ __half g_ATTOh[N1 * CC];
__device__ __half g_H2h[N1 * CC];
__device__ __half g_FF1h[N1 * 2 * CC];

// half weights
__device__ __half g_embWh[CC * INDIM];
__device__ __half g_sageWh[NL * CC * 2 * CC];
__device__ __half g_qkvWh[NL * 3 * CC * CC];
__device__ __half g_outWh[NL * CC * CC];
__device__ __half g_ffnW1h[NL * 2 * CC * CC];
__device__ __half g_ffnW2h[NL * CC * 2 * CC];
__device__ __half g_clsWh[NC * CC];
__device__ __half g_feats0h[N0 * INDIM];
__device__ __half g_feats1h[N1 * INDIM];

// ---------------------------------------------------------------------------
// helpers
// ---------------------------------------------------------------------------
__device__ __forceinline__ void mma_f16(float* d, const uint32_t* a, const uint32_t* b,
                                        const float* c) {
    asm volatile(
        "mma.sync.aligned.m16n8k16.row.col.f32.f16.f16.f32 "
        "{%0,%1,%2,%3}, {%4,%5,%6,%7}, {%8,%9}, {%10,%11,%12,%13};\n"
        : "=f"(d[0]), "=f"(d[1]), "=f"(d[2]), "=f"(d[3])
        : "r"(a[0]), "r"(a[1]), "r"(a[2]), "r"(a[3]),
          "r"(b[0]), "r"(b[1]),
          "f"(c[0]), "f"(c[1]), "f"(c[2]), "f"(c[3]));
}

__device__ __forceinline__ void ldsm_x4(uint32_t& r0, uint32_t& r1, uint32_t& r2,
                                        uint32_t& r3, uint32_t addr) {
    asm volatile("ldmatrix.sync.aligned.m8n8.x4.shared.b16 {%0,%1,%2,%3}, [%4];"
                 : "=r"(r0), "=r"(r1), "=r"(r2), "=r"(r3) : "r"(addr));
}
__device__ __forceinline__ void ldsm_x4_t(uint32_t& r0, uint32_t& r1, uint32_t& r2,
                                          uint32_t& r3, uint32_t addr) {
    asm volatile("ldmatrix.sync.aligned.m8n8.x4.trans.shared.b16 {%0,%1,%2,%3}, [%4];"
                 : "=r"(r0), "=r"(r1), "=r"(r2), "=r"(r3) : "r"(addr));
}

__device__ __forceinline__ void cpa16(void* smemDst, const void* gsrc, int srcBytes) {
    uint32_t saddr = (uint32_t)__cvta_generic_to_shared(smemDst);
    asm volatile("cp.async.cg.shared.global [%0], [%1], 16, %2;\n"
                 :: "r"(saddr), "l"(gsrc), "r"(srcBytes));
}
__device__ __forceinline__ void cpa_commit() { asm volatile("cp.async.commit_group;\n"); }
__device__ __forceinline__ void cpa_wait2() { asm volatile("cp.async.wait_group 2;\n"); }
__device__ __forceinline__ void cpa_wait1() { asm volatile("cp.async.wait_group 1;\n"); }
__device__ __forceinline__ void cpa_wait0() { asm volatile("cp.async.wait_group 0;\n"); }

__device__ __forceinline__ uint32_t scale_h2(uint32_t u, float s) {
    __half2 hv = *reinterpret_cast<const __half2*>(&u);
    float2 f = __half22float2(hv);
    __half2 o = __floats2half2_rn(f.x * s, f.y * s);
    return *reinterpret_cast<uint32_t*>(&o);
}
__device__ __forceinline__ uint32_t pack_h2(float a, float b) {
    __half2 o = __floats2half2_rn(a, b);
    return *reinterpret_cast<uint32_t*>(&o);
}

// ---------------------------------------------------------------------------
// fp16 cp.async GEMM (R12-proven): CTA 128x64x32, 256 thr / 8 warps (4m x 2n),
// warp tile 32x32, ldmatrix frag loads, 4 stages, 2 CTAs/SM.
// C = [A | A2](half) x B^T(half) + epilogue.
// ---------------------------------------------------------------------------
#define GBM 128
#define GBN 64
#define KT 32
#define APH 40                         // halves per smem row (32 + 8 pad) = 80 B
#define STAGES 4
#define STAGE_H ((GBM + GBN) * APH)    // 7680 halves = 15360 B
#define GEMM_SMEM (STAGES * STAGE_H * 2)

__global__ void __launch_bounds__(256, 2) gemm_f16_kernel(
    int M, int N, int K,
    const __half* __restrict__ A, int lda,
    const __half* __restrict__ A2, int kSplit,
    const __half* __restrict__ B, int ldb,
    float* __restrict__ C, __half* __restrict__ Ch, int ldc,
    const float* __restrict__ bias,
    const float* __restrict__ biasScale,
    int relu,
    const float* __restrict__ addC,
    const float* __restrict__ rowMask)
{
    extern __shared__ __half smh[];

    const int bm = blockIdx.y * GBM;
    const int bn = blockIdx.x * GBN;
    const int t = threadIdx.x;
    const int lane = t & 31;
    const int wid = t >> 5;
    const int q = lane >> 2;
    const int r = lane & 3;
    const int grp = lane >> 3;   // 0..3
    const int lr = lane & 7;
    const int wm = (wid & 3) * 32;
    const int wn = (wid >> 2) * 32;

    float acc[2][4][4];
    #pragma unroll
    for (int mi = 0; mi < 2; mi++)
        #pragma unroll
        for (int ni = 0; ni < 4; ni++)
            #pragma unroll
            for (int e = 0; e < 4; e++) acc[mi][ni][e] = 0.0f;

    auto issueStage = [&](int buf, int k0) {
        __half* sA = smh + buf * STAGE_H;
        __half* sB = sA + GBM * APH;
        const __half* Asrc = (k0 < kSplit) ? A : A2;
        const int kk = (k0 < kSplit) ? k0 : (k0 - kSplit);
        #pragma unroll
        for (int i = 0; i < 2; i++) {
            int idx = t + 256 * i;
            int row = idx >> 2;
            int c8 = (idx & 3) * 8;
            int gm = bm + row;
            int ok = (gm < M);
            cpa16(sA + row * APH + c8,
                  Asrc + (long long)(ok ? gm : 0) * lda + kk + c8, ok ? 16 : 0);
        }
        {
            int row = t >> 2;
            int c8 = (t & 3) * 8;
            int gn = bn + row;
            int ok = (gn < N);
            cpa16(sB + row * APH + c8,
                  B + (long long)(ok ? gn : 0) * ldb + k0 + c8, ok ? 16 : 0);
        }
    };

    auto computeStage = [&](int buf) {
        const uint32_t sa = (uint32_t)__cvta_generic_to_shared(smh + buf * STAGE_H);
        const uint32_t sb = (uint32_t)__cvta_generic_to_shared(smh + buf * STAGE_H + GBM * APH);
        #pragma unroll
        for (int ks = 0; ks < 2; ks++) {
            const int kb = ks * 16;
            uint32_t af[2][4], bf[4][2];
            #pragma unroll
            for (int mi = 0; mi < 2; mi++) {
                int arow = wm + mi * 16 + ((grp & 1) ? 8 : 0) + lr;
                int acol = kb + ((grp & 2) ? 8 : 0);
                ldsm_x4(af[mi][0], af[mi][1], af[mi][2], af[mi][3],
                        sa + (arow * APH + acol) * 2);
            }
            #pragma unroll
            for (int nfp = 0; nfp < 2; nfp++) {
                int brow = wn + nfp * 16 + ((grp & 2) ? 8 : 0) + lr;
                int bcol = kb + ((grp & 1) ? 8 : 0);
                uint32_t b0, b1, b2, b3;
                ldsm_x4(b0, b1, b2, b3, sb + (brow * APH + bcol) * 2);
                bf[2 * nfp][0] = b0;      bf[2 * nfp][1] = b1;
                bf[2 * nfp + 1][0] = b2;  bf[2 * nfp + 1][1] = b3;
            }
            #pragma unroll
            for (int mi = 0; mi < 2; mi++)
                #pragma unroll
                for (int ni = 0; ni < 4; ni++)
                    mma_f16(acc[mi][ni], af[mi], bf[ni], acc[mi][ni]);
        }
    };

    const int ntiles = K / KT;
    #pragma unroll
    for (int s = 0; s < STAGES - 1; s++) {
        if (s < ntiles) issueStage(s, s * KT);
        cpa_commit();
    }
    for (int it = 0; it < ntiles; it++) {
        cpa_wait2();
        __syncthreads();
        const int nj = it + STAGES - 1;
        if (nj < ntiles) issueStage(nj & (STAGES - 1), nj * KT);
        cpa_commit();
        computeStage(it & (STAGES - 1));
    }

    // ---- epilogue ----
    #pragma unroll
    for (int mi = 0; mi < 2; mi++) {
        #pragma unroll
        for (int hh = 0; hh < 2; hh++) {
            int gm = bm + wm + mi * 16 + q + hh * 8;
            if (gm >= M) continue;
            float bs = biasScale ? biasScale[gm] : 1.0f;
            float rmv = rowMask ? rowMask[gm] : 1.0f;
            #pragma unroll
            for (int ni = 0; ni < 4; ni++) {
                int gn0 = bn + wn + ni * 8 + 2 * r;
                if (gn0 >= N) continue;
                float v[2];
                #pragma unroll
                for (int j = 0; j < 2; j++) {
                    int gn = gn0 + j;
                    float x = acc[mi][ni][hh * 2 + j];
                    if (bias && gn < N) x += bias[gn] * bs;
                    if (relu) x = fmaxf(x, 0.0f);
                    if (addC && gn < N) x += addC[(long long)gm * ldc + gn];
                    v[j] = x * rmv;
                }
                if (C) {
                    C[(long long)gm * ldc + gn0] = v[0];
                    if (gn0 + 1 < N) C[(long long)gm * ldc + gn0 + 1] = v[1];
                }
                if (Ch) {
                    *reinterpret_cast<__half2*>(Ch + (long long)gm * ldc + gn0) =
                        __floats2half2_rn(v[0], v[1]);
                }
            }
        }
    }
}

// ---------------------------------------------------------------------------
// fp16 flash attention, double-buffered K/V (R12-proven).
// CTA = 64 query rows x 1 head, 128 thr / 4 warps; KV tiles of 64.
// ---------------------------------------------------------------------------
#define FPITCH_H 136
#define FL_STAGE_H (2 * 64 * FPITCH_H)
#define FLASH_SMEM (2 * FL_STAGE_H * 2)

__global__ void __launch_bounds__(128) flash_f16_kernel(
    const __half* __restrict__ QKV, __half* __restrict__ O, int n)
{
    extern __shared__ __half fsm[];

    const int t = threadIdx.x;
    const int warp = t >> 5;
    const int lane = t & 31;
    const int q = lane >> 2;
    const int r = lane & 3;
    const int head = blockIdx.y;
    const int qbase = blockIdx.x * 64;
    const int row0 = warp * 16 + q;
    const float scale = 0.08838834764831845f;

    const uint32_t sbase = (uint32_t)__cvta_generic_to_shared(fsm);

    auto issueKV = [&](int kt, int buf) {
        __half* sK = fsm + buf * FL_STAGE_H;
        __half* sV = sK + 64 * FPITCH_H;
        #pragma unroll
        for (int i = 0; i < 8; i++) {
            int idx = t + 128 * i;
            int row = idx >> 4;
            int c8 = (idx & 15) * 8;
            const __half* kp = QKV + (long long)(kt * 64 + row) * (3 * CC) + CC + head * DH + c8;
            cpa16(sK + row * FPITCH_H + c8, kp, 16);
            cpa16(sV + row * FPITCH_H + c8, kp + CC, 16);
        }
    };

    uint32_t qf[8][4];
    {
        const __half* q0p = QKV + (long long)(qbase + row0) * (3 * CC) + head * DH;
        const __half* q1p = q0p + 8LL * (3 * CC);
        #pragma unroll
        for (int kc = 0; kc < 8; kc++) {
            qf[kc][0] = scale_h2(*(const uint32_t*)(q0p + kc * 16 + 2 * r), scale);
            qf[kc][1] = scale_h2(*(const uint32_t*)(q1p + kc * 16 + 2 * r), scale);
            qf[kc][2] = scale_h2(*(const uint32_t*)(q0p + kc * 16 + 2 * r + 8), scale);
            qf[kc][3] = scale_h2(*(const uint32_t*)(q1p + kc * 16 + 2 * r + 8), scale);
        }
    }

    float oacc[16][4];
    #pragma unroll
    for (int df = 0; df < 16; df++)
        #pragma unroll
        for (int e = 0; e < 4; e++) oacc[df][e] = 0.0f;
    float m0 = -1e30f, m1 = -1e30f, l0 = 0.0f, l1 = 0.0f;

    const int grp = lane >> 3;
    const int lr = lane & 7;

    const int ntiles = n / 64;
    issueKV(0, 0);
    cpa_commit();

    for (int kt = 0; kt < ntiles; kt++) {
        if (kt + 1 < ntiles) {
            issueKV(kt + 1, (kt + 1) & 1);
            cpa_commit();
            cpa_wait1();
        } else {
            cpa_wait0();
        }
        __syncthreads();

        const uint32_t skb = sbase + ((kt & 1) * FL_STAGE_H) * 2;
        const uint32_t svb = skb + 64 * FPITCH_H * 2;

        float sacc[8][4];
        #pragma unroll
        for (int nf = 0; nf < 8; nf++)
            #pragma unroll
            for (int e = 0; e < 4; e++) sacc[nf][e] = 0.0f;
        #pragma unroll
        for (int kc = 0; kc < 8; kc++) {
            #pragma unroll
            for (int nfp = 0; nfp < 4; nfp++) {
                int kvr = nfp * 16 + ((grp & 2) ? 8 : 0) + lr;
                int dc = kc * 16 + ((grp & 1) ? 8 : 0);
                uint32_t b0, b1, b2, b3;
                ldsm_x4(b0, b1, b2, b3, skb + (kvr * FPITCH_H + dc) * 2);
                uint32_t bA[2] = {b0, b1}, bB[2] = {b2, b3};
                mma_f16(sacc[2 * nfp], qf[kc], bA, sacc[2 * nfp]);
                mma_f16(sacc[2 * nfp + 1], qf[kc], bB, sacc[2 * nfp + 1]);
            }
        }

        float tm0 = -1e30f, tm1 = -1e30f;
        #pragma unroll
        for (int nf = 0; nf < 8; nf++) {
            tm0 = fmaxf(tm0, fmaxf(sacc[nf][0], sacc[nf][1]));
            tm1 = fmaxf(tm1, fmaxf(sacc[nf][2], sacc[nf][3]));
        }
        tm0 = fmaxf(tm0, __shfl_xor_sync(0xffffffffu, tm0, 1));
        tm0 = fmaxf(tm0, __shfl_xor_sync(0xffffffffu, tm0, 2));
        tm1 = fmaxf(tm1, __shfl_xor_sync(0xffffffffu, tm1, 1));
        tm1 = fmaxf(tm1, __shfl_xor_sync(0xffffffffu, tm1, 2));
        const float nm0 = fmaxf(m0, tm0);
        const float nm1 = fmaxf(m1, tm1);
        const float cor0 = __expf(m0 - nm0);
        const float cor1 = __expf(m1 - nm1);
        m0 = nm0; m1 = nm1;

        float ts0 = 0.0f, ts1 = 0.0f;
        #pragma unroll
        for (int nf = 0; nf < 8; nf++) {
            sacc[nf][0] = __expf(sacc[nf][0] - m0);
            sacc[nf][1] = __expf(sacc[nf][1] - m0);
            sacc[nf][2] = __expf(sacc[nf][2] - m1);
            sacc[nf][3] = __expf(sacc[nf][3] - m1);
            ts0 += sacc[nf][0] + sacc[nf][1];
            ts1 += sacc[nf][2] + sacc[nf][3];
        }
        ts0 += __shfl_xor_sync(0xffffffffu, ts0, 1);
        ts0 += __shfl_xor_sync(0xffffffffu, ts0, 2);
        ts1 += __shfl_xor_sync(0xffffffffu, ts1, 1);
        ts1 += __shfl_xor_sync(0xffffffffu, ts1, 2);
        l0 = l0 * cor0 + ts0;
        l1 = l1 * cor1 + ts1;

        uint32_t pf[4][4];
        #pragma unroll
        for (int j = 0; j < 4; j++) {
            pf[j][0] = pack_h2(sacc[2 * j][0], sacc[2 * j][1]);
            pf[j][1] = pack_h2(sacc[2 * j][2], sacc[2 * j][3]);
            pf[j][2] = pack_h2(sacc[2 * j + 1][0], sacc[2 * j + 1][1]);
            pf[j][3] = pack_h2(sacc[2 * j + 1][2], sacc[2 * j + 1][3]);
        }

        #pragma unroll
        for (int df = 0; df < 16; df++) {
            oacc[df][0] *= cor0; oacc[df][1] *= cor0;
            oacc[df][2] *= cor1; oacc[df][3] *= cor1;
        }

        #pragma unroll
        for (int j = 0; j < 4; j++) {
            #pragma unroll
            for (int dfp = 0; dfp < 8; dfp++) {
                int kvr = 16 * j + ((grp & 1) ? 8 : 0) + lr;
                int dc = dfp * 16 + ((grp & 2) ? 8 : 0);
                uint32_t b0, b1, b2, b3;
                ldsm_x4_t(b0, b1, b2, b3, svb + (kvr * FPITCH_H + dc) * 2);
                uint32_t bA[2] = {b0, b1}, bB[2] = {b2, b3};
                mma_f16(oacc[2 * dfp], pf[j], bA, oacc[2 * dfp]);
                mma_f16(oacc[2 * dfp + 1], pf[j], bB, oacc[2 * dfp + 1]);
            }
        }
        __syncthreads();
    }

    const float inv0 = 1.0f / l0;
    const float inv1 = 1.0f / l1;
    #pragma unroll
    for (int df = 0; df < 16; df++) {
        const int gc = head * DH + df * 8 + 2 * r;
        *reinterpret_cast<__half2*>(O + (long long)(qbase + row0) * CC + gc) =
            __floats2half2_rn(oacc[df][0] * inv0, oacc[df][1] * inv0);
        *reinterpret_cast<__half2*>(O + (long long)(qbase + row0 + 8) * CC + gc) =
            __floats2half2_rn(oacc[df][2] * inv1, oacc[df][3] * inv1);
    }
}

// ---------------------------------------------------------------------------
// Block reduction (128 threads, 4 warps)
// ---------------------------------------------------------------------------
__device__ __forceinline__ float blockReduceSum128(float v, float* red) {
    #pragma unroll
    for (int o = 16; o > 0; o >>= 1) v += __shfl_xor_sync(0xffffffffu, v, o);
    int w = threadIdx.x >> 5;
    if ((threadIdx.x & 31) == 0) red[w] = v;
    __syncthreads();
    float rr;
    if (threadIdx.x < 32) {
        rr = (threadIdx.x < 4) ? red[threadIdx.x] : 0.0f;
        #pragma unroll
        for (int o = 2; o > 0; o >>= 1) rr += __shfl_xor_sync(0xffffffffu, rr, o);
        if (threadIdx.x == 0) red[0] = rr;
    }
    __syncthreads();
    rr = red[0];
    __syncthreads();
    return rr;
}

// ---------------------------------------------------------------------------
// LN(a+b)*g+beta -> fp32 out + half out. 128 threads, float4-vectorized.
// ---------------------------------------------------------------------------
__global__ void add_ln_kernel(const float* __restrict__ a, const float* __restrict__ b,
                              const float* __restrict__ g, const float* __restrict__ be,
                              float* __restrict__ out, __half* __restrict__ outH)
{
    long long row = blockIdx.x;
    const float4* a4 = (const float4*)(a + row * CC);
    const float4* b4 = (const float4*)(b + row * CC);
    int tid = threadIdx.x;   // 0..127, each handles one float4 (CC/4 = 128)

    float4 av = a4[tid];
    float4 bv = b4[tid];
    float4 x;
    x.x = av.x + bv.x; x.y = av.y + bv.y; x.z = av.z + bv.z; x.w = av.w + bv.w;

    __shared__ float red[4];
    float mu = blockReduceSum128(x.x + x.y + x.z + x.w, red) * (1.0f / CC);
    float dx = x.x - mu, dy = x.y - mu, dz = x.z - mu, dw = x.w - mu;
    float var = blockReduceSum128(dx * dx + dy * dy + dz * dz + dw * dw, red) * (1.0f / CC);
    float rstd = rsqrtf(var + 1e-5f);

    const float4 gv = ((const float4*)g)[tid];
    const float4 bev = ((const float4*)be)[tid];
    float4 y;
    y.x = dx * rstd * gv.x + bev.x;
    y.y = dy * rstd * gv.y + bev.y;
    y.z = dz * rstd * gv.z + bev.z;
    y.w = dw * rstd * gv.w + bev.w;

    ((float4*)(out + row * CC))[tid] = y;
    __half2 h0 = __floats2half2_rn(y.x, y.y);
    __half2 h1 = __floats2half2_rn(y.z, y.w);
    uint2 ho;
    ho.x = *reinterpret_cast<uint32_t*>(&h0);
    ho.y = *reinterpret_cast<uint32_t*>(&h1);
    ((uint2*)(outH + row * CC))[tid] = ho;
}

// ---------------------------------------------------------------------------
// Masked-mean aggregation, vectorized float4 -> half2 out (+ optional coef)
// ---------------------------------------------------------------------------
__global__ void agg_kernel(const float* __restrict__ X, int C,
                           const int* __restrict__ nbm,
                           const float* __restrict__ childMask,
                           __half* __restrict__ out, float* __restrict__ coefOut, int P)
{
    int C4 = C >> 2;
    long long idx = (long long)blockIdx.x * blockDim.x + threadIdx.x;
    if (idx >= (long long)P * C4) return;
    int p = (int)(idx / C4);
    int c4 = (int)(idx % C4);
    const float4* X4 = (const float4*)X;
    float4 sum = make_float4(0.f, 0.f, 0.f, 0.f);
    float den = 0.0f, wsum = 0.0f;
    #pragma unroll
    for (int f = 0; f < FAN; f++) {
        float nb = (float)nbm[p * FAN + f];
        den += nb;
        float w = nb * (childMask ? childMask[p * FAN + f] : 1.0f);
        wsum += w;
        float4 v = X4[(long long)(p * FAN + f) * C4 + c4];
        sum.x += w * v.x; sum.y += w * v.y; sum.z += w * v.z; sum.w += w * v.w;
    }
    den = fmaxf(den, 1.0f);
    float inv = 1.0f / den;
    __half2 a = __floats2half2_rn(sum.x * inv, sum.y * inv);
    __half2 b = __floats2half2_rn(sum.z * inv, sum.w * inv);
    uint2 o;
    o.x = *reinterpret_cast<uint32_t*>(&a);
    o.y = *reinterpret_cast<uint32_t*>(&b);
    ((uint2*)out)[(long long)p * C4 + c4] = o;
    if (coefOut && c4 == 0) coefOut[p] = wsum * inv;
}

// ---------------------------------------------------------------------------
// Multi-segment vectorized fp32 -> fp16 conversion
// ---------------------------------------------------------------------------
#define MAXSEG 12
struct CvtJobs {
    const float* src[MAXSEG];
    __half* dst[MAXSEG];
    int quads[MAXSEG];
    int nseg;
};

__global__ void cvt_multi_kernel(CvtJobs jobs)
{
    int seg = blockIdx.y;
    if (seg >= jobs.nseg) return;
    const float4* src = (const float4*)jobs.src[seg];
    uint2* dst = (uint2*)jobs.dst[seg];
    int nq = jobs.quads[seg];
    for (int i = blockIdx.x * blockDim.x + threadIdx.x; i < nq; i += gridDim.x * blockDim.x) {
        float4 v = src[i];
        __half2 a = __floats2half2_rn(v.x, v.y);
        __half2 b = __floats2half2_rn(v.z, v.w);
        uint2 o;
        o.x = *reinterpret_cast<uint32_t*>(&a);
        o.y = *reinterpret_cast<uint32_t*>(&b);
        dst[i] = o;
    }
}

// ---------------------------------------------------------------------------
// Host orchestration
// ---------------------------------------------------------------------------
static void gemm(int M, int N, int K,
                 const __half* A, int lda, const __half* A2, int kSplit,
                 const __half* B, int ldb,
                 float* C, __half* Ch, int ldc,
                 const float* bias, const float* biasScale, int relu,
                 const float* addC, const float* rowMask)
{
    dim3 grid((N + GBN - 1) / GBN, (M + GBM - 1) / GBM);
    gemm_f16_kernel<<<grid, 256, GEMM_SMEM>>>(
        M, N, K, A, lda, A2, kSplit, B, ldb, C, Ch, ldc,
        bias, biasScale, relu, addC, rowMask);
}

struct Scratch {
    float *S1E, *S1N, *S0, *AGGC, *HL, *H1, *ATT, *H2;
    __half *S1Eh, *S0h, *AGGFh, *AGGh, *H1h, *QKVh, *ATTOh, *H2h, *FF1h;
    __half *embWh, *sageWh, *qkvWh, *outWh, *ffnW1h, *ffnW2h, *clsWh, *feats0h, *feats1h;
};

static Scratch get_scratch() {
    Scratch s; void* p;
    cudaGetSymbolAddress(&p, g_S1E);    s.S1E    = (float*)p;
    cudaGetSymbolAddress(&p, g_S1N);    s.S1N    = (float*)p;
    cudaGetSymbolAddress(&p, g_S0);     s.S0     = (float*)p;
    cudaGetSymbolAddress(&p, g_AGGC);   s.AGGC   = (float*)p;
    cudaGetSymbolAddress(&p, g_HL);     s.HL     = (float*)p;
    cudaGetSymbolAddress(&p, g_H1);     s.H1     = (float*)p;
    cudaGetSymbolAddress(&p, g_ATT);    s.ATT    = (float*)p;
    cudaGetSymbolAddress(&p, g_H2);     s.H2     = (float*)p;
    cudaGetSymbolAddress(&p, g_S1Eh);   s.S1Eh   = (__half*)p;
    cudaGetSymbolAddress(&p, g_S0h);    s.S0h    = (__half*)p;
    cudaGetSymbolAddress(&p, g_AGGFh);  s.AGGFh  = (__half*)p;
    cudaGetSymbolAddress(&p, g_AGGh);   s.AGGh   = (__half*)p;
    cudaGetSymbolAddress(&p, g_H1h);    s.H1h    = (__half*)p;
    cudaGetSymbolAddress(&p, g_QKVh);   s.QKVh   = (__half*)p;
    cudaGetSymbolAddress(&p, g_ATTOh);  s.ATTOh  = (__half*)p;
    cudaGetSymbolAddress(&p, g_H2h);    s.H2h    = (__half*)p;
    cudaGetSymbolAddress(&p, g_FF1h);   s.FF1h   = (__half*)p;
    cudaGetSymbolAddress(&p, g_embWh);  s.embWh  = (__half*)p;
    cudaGetSymbolAddress(&p, g_sageWh); s.sageWh = (__half*)p;
    cudaGetSymbolAddress(&p, g_qkvWh);  s.qkvWh  = (__half*)p;
    cudaGetSymbolAddress(&p, g_outWh);  s.outWh  = (__half*)p;
    cudaGetSymbolAddress(&p, g_ffnW1h); s.ffnW1h = (__half*)p;
    cudaGetSymbolAddress(&p, g_ffnW2h); s.ffnW2h = (__half*)p;
    cudaGetSymbolAddress(&p, g_clsWh);  s.clsWh  = (__half*)p;
    cudaGetSymbolAddress(&p, g_feats0h); s.feats0h = (__half*)p;
    cudaGetSymbolAddress(&p, g_feats1h); s.feats1h = (__half*)p;
    return s;
}

struct LayerW {
    const __half *sageW, *qkvW, *outW, *ffnW1, *ffnW2;
    const float *sageB, *qkvB, *outB, *ffnB1, *ffnB2;
    const float *n1g, *n1b, *n2g, *n2b;
};

static void block_forward(int n, const float* sf, const __half* sfh, const __half* agg,
                          float* outState, __half* outStateH,
                          const float* rowMask, const LayerW& w, const Scratch& s)
{
    gemm(n, CC, 2 * CC, sfh, CC, agg, CC, w.sageW, 2 * CC,
         s.HL, nullptr, CC, w.sageB, nullptr, 0, nullptr, nullptr);
    add_ln_kernel<<<n, 128>>>(sf, s.HL, w.n1g, w.n1b, s.H1, s.H1h);

    gemm(n, 3 * CC, CC, s.H1h, CC, nullptr, CC, w.qkvW, CC,
         nullptr, s.QKVh, 3 * CC, w.qkvB, nullptr, 0, nullptr, nullptr);

    {
        dim3 grid(n / 64, HH);
        flash_f16_kernel<<<grid, 128, FLASH_SMEM>>>(s.QKVh, s.ATTOh, n);
    }

    gemm(n, CC, CC, s.ATTOh, CC, nullptr, CC, w.outW, CC,
         s.ATT, nullptr, CC, w.outB, nullptr, 0, nullptr, nullptr);
    add_ln_kernel<<<n, 128>>>(s.H1, s.ATT, w.n2g, w.n2b, s.H2, s.H2h);

    gemm(n, 2 * CC, CC, s.H2h, CC, nullptr, CC, w.ffnW1, CC,
         nullptr, s.FF1h, 2 * CC, w.ffnB1, nullptr, 1, nullptr, nullptr);
    gemm(n, CC, 2 * CC, s.FF1h, 2 * CC, nullptr, 2 * CC, w.ffnW2, 2 * CC,
         outState, outStateH, CC, w.ffnB2, nullptr, 0, s.H2, rowMask);
}

extern "C" void kernel_launch(void* const* d_in, const int* in_sizes, int n_in,
                              void* d_out, int out_size)
{
    const float* feats0  = (const float*)d_in[0];
    const float* feats1  = (const float*)d_in[1];
    const float* feats2  = (const float*)d_in[2];
    const float* nmask0  = (const float*)d_in[3];
    const float* nmask1  = (const float*)d_in[4];
    const float* nmask2  = (const float*)d_in[5];
    const int*   nbmask0 = (const int*)d_in[6];
    const int*   nbmask1 = (const int*)d_in[7];
    const float* emb_w   = (const float*)d_in[8];
    const float* emb_b   = (const float*)d_in[9];
    const float* sage_w  = (const float*)d_in[10];
    const float* sage_b  = (const float*)d_in[11];
    const float* qkv_w   = (const float*)d_in[12];
    const float* qkv_b   = (const float*)d_in[13];
    const float* out_w   = (const float*)d_in[14];
    const float* out_b   = (const float*)d_in[15];
    const float* n1_g    = (const float*)d_in[16];
    const float* n1_b    = (const float*)d_in[17];
    const float* n2_g    = (const float*)d_in[18];
    const float* n2_b    = (const float*)d_in[19];
    const float* ffn_w1  = (const float*)d_in[20];
    const float* ffn_b1  = (const float*)d_in[21];
    const float* ffn_w2  = (const float*)d_in[22];
    const float* ffn_b2  = (const float*)d_in[23];
    const float* cls_w   = (const float*)d_in[24];
    const float* cls_b   = (const float*)d_in[25];
    float* out = (float*)d_out;

    cudaFuncSetAttribute(gemm_f16_kernel, cudaFuncAttributeMaxDynamicSharedMemorySize,
                         GEMM_SMEM);
    cudaFuncSetAttribute(flash_f16_kernel, cudaFuncAttributeMaxDynamicSharedMemorySize,
                         FLASH_SMEM);

    Scratch s = get_scratch();

    // ---- all fp32->fp16 conversions in one vectorized launch ----
    {
        CvtJobs j;
        j.src[0] = emb_w;   j.dst[0] = s.embWh;   j.quads[0] = CC * INDIM / 4;
        j.src[1] = sage_w;  j.dst[1] = s.sageWh;  j.quads[1] = NL * CC * 2 * CC / 4;
        j.src[2] = qkv_w;   j.dst[2] = s.qkvWh;   j.quads[2] = NL * 3 * CC * CC / 4;
        j.src[3] = out_w;   j.dst[3] = s.outWh;   j.quads[3] = NL * CC * CC / 4;
        j.src[4] = ffn_w1;  j.dst[4] = s.ffnW1h;  j.quads[4] = NL * 2 * CC * CC / 4;
        j.src[5] = ffn_w2;  j.dst[5] = s.ffnW2h;  j.quads[5] = NL * CC * 2 * CC / 4;
        j.src[6] = cls_w;   j.dst[6] = s.clsWh;   j.quads[6] = NC * CC / 4;
        j.src[7] = feats0;  j.dst[7] = s.feats0h; j.quads[7] = N0 * INDIM / 4;
        j.src[8] = feats1;  j.dst[8] = s.feats1h; j.quads[8] = N1 * INDIM / 4;
        j.nseg = 9;
        for (int i = j.nseg; i < MAXSEG; i++) { j.src[i] = nullptr; j.dst[i] = nullptr; j.quads[i] = 0; }
        dim3 grid(128, j.nseg);
        cvt_multi_kernel<<<grid, 256>>>(j);
    }

    LayerW w[NL];
    for (int li = 0; li < NL; li++) {
        w[li].sageW = s.sageWh + (long long)li * CC * 2 * CC;
        w[li].qkvW  = s.qkvWh  + (long long)li * 3 * CC * CC;
        w[li].outW  = s.outWh  + (long long)li * CC * CC;
        w[li].ffnW1 = s.ffnW1h + (long long)li * 2 * CC * CC;
        w[li].ffnW2 = s.ffnW2h + (long long)li * CC * 2 * CC;
        w[li].sageB = sage_b + li * CC;
        w[li].qkvB  = qkv_b  + li * 3 * CC;
        w[li].outB  = out_b  + li * CC;
        w[li].ffnB1 = ffn_b1 + li * 2 * CC;
        w[li].ffnB2 = ffn_b2 + li * CC;
        w[li].n1g = n1_g + li * CC;  w[li].n1b = n1_b + li * CC;
        w[li].n2g = n2_g + li * CC;  w[li].n2b = n2_b + li * CC;
    }

    // ---- embeddings (depth 0, 1), masked; write fp32 + half ----
    gemm(N0, CC, INDIM, s.feats0h, INDIM, nullptr, INDIM, s.embWh, INDIM,
         s.S0, s.S0h, CC, emb_b, nullptr, 0, nullptr, nmask0);
    gemm(N1, CC, INDIM, s.feats1h, INDIM, nullptr, INDIM, s.embWh, INDIM,
         s.S1E, s.S1Eh, CC, emb_b, nullptr, 0, nullptr, nmask1);

    // ---- depth-2: aggregate RAW feats2 then one embedding GEMM ----
    agg_kernel<<<(int)(((long long)N1 * INDIM / 4 + 255) / 256), 256>>>(
        feats2, INDIM, nbmask1, nmask2, s.AGGFh, s.AGGC, N1);
    gemm(N1, CC, INDIM, s.AGGFh, INDIM, nullptr, INDIM, s.embWh, INDIM,
         nullptr, s.AGGh, CC, emb_b, s.AGGC, 0, nullptr, nullptr);

    // ---- layer 0, depth 1 (n=4096) ----
    block_forward(N1, s.S1E, s.S1Eh, s.AGGh, s.S1N, nullptr, nmask1, w[0], s);

    // ---- layer 0, depth 0 ----
    agg_kernel<<<(int)(((long long)N0 * CC / 4 + 255) / 256), 256>>>(
        s.S1E, CC, nbmask0, nullptr, s.AGGh, nullptr, N0);
    block_forward(N0, s.S0, s.S0h, s.AGGh, s.S0, s.S0h, nmask0, w[0], s);

    // ---- layer 1, depth 0 ----
    agg_kernel<<<(int)(((long long)N0 * CC / 4 + 255) / 256), 256>>>(
        s.S1N, CC, nbmask0, nullptr, s.AGGh, nullptr, N0);
    block_forward(N0, s.S0, s.S0h, s.AGGh, s.S0, s.S0h, nmask0, w[1], s);

    // ---- classifier ----
    gemm(N0, NC, CC, s.S0h, CC, nullptr, CC, s.clsWh, CC,
         out, nullptr, NC, cls_b, nullptr, 0, nullptr, nullptr);
}

// round 15
// speedup vs baseline: 1.1410x; 1.0285x over previous
#include <cuda_runtime.h>
#include <cuda_fp16.h>
#include <math.h>
#include <stdint.h>

// ---------------------------------------------------------------------------
// Problem constants
// ---------------------------------------------------------------------------
#define NL 2
#define HH 4
#define CC 512
#define INDIM 256
#define FAN 16
#define NC 47
#define DH 128
#define N0 256
#define N1 4096

// ---------------------------------------------------------------------------
// Device scratch (fp32 + half mirrors)
// ---------------------------------------------------------------------------
__device__ float g_S1E[N1 * CC];
__device__ float g_S1N[N1 * CC];
__device__ float g_S0[N0 * CC];
__device__ float g_AGGC[N1];
__device__ float g_HL[N1 * CC];
__device__ float g_H1[N1 * CC];
__device__ float g_ATT[N1 * CC];
__device__ float g_H2[N1 * CC];

__device__ __half g_S1Eh[N1 * CC];
__device__ __half g_S0h[N0 * CC];
__device__ __half g_AGGFh[N1 * INDIM];
__device__ __half g_AGGh[N1 * CC];
__device__ __half g_H1h[N1 * CC];
__device__ __half g_QKVh[N1 * 3 * CC];
__device__ __half g_ATTOh[N1 * CC];
__device__ __half g_H2h[N1 * CC];
__device__ __half g_FF1h[N1 * 2 * CC];

// half weights
__device__ __half g_embWh[CC * INDIM];
__device__ __half g_sageWh[NL * CC * 2 * CC];
__device__ __half g_qkvWh[NL * 3 * CC * CC];
__device__ __half g_outWh[NL * CC * CC];
__device__ __half g_ffnW1h[NL * 2 * CC * CC];
__device__ __half g_ffnW2h[NL * CC * 2 * CC];
__device__ __half g_clsWh[NC * CC];
__device__ __half g_feats0h[N0 * INDIM];
__device__ __half g_feats1h[N1 * INDIM];

// ---------------------------------------------------------------------------
// helpers
// ---------------------------------------------------------------------------
__device__ __forceinline__ void mma_f16(float* d, const uint32_t* a, const uint32_t* b,
                                        const float* c) {
    asm volatile(
        "mma.sync.aligned.m16n8k16.row.col.f32.f16.f16.f32 "
        "{%0,%1,%2,%3}, {%4,%5,%6,%7}, {%8,%9}, {%10,%11,%12,%13};\n"
        : "=f"(d[0]), "=f"(d[1]), "=f"(d[2]), "=f"(d[3])
        : "r"(a[0]), "r"(a[1]), "r"(a[2]), "r"(a[3]),
          "r"(b[0]), "r"(b[1]),
          "f"(c[0]), "f"(c[1]), "f"(c[2]), "f"(c[3]));
}

__device__ __forceinline__ void ldsm_x4(uint32_t& r0, uint32_t& r1, uint32_t& r2,
                                        uint32_t& r3, uint32_t addr) {
    asm volatile("ldmatrix.sync.aligned.m8n8.x4.shared.b16 {%0,%1,%2,%3}, [%4];"
                 : "=r"(r0), "=r"(r1), "=r"(r2), "=r"(r3) : "r"(addr));
}
__device__ __forceinline__ void ldsm_x4_t(uint32_t& r0, uint32_t& r1, uint32_t& r2,
                                          uint32_t& r3, uint32_t addr) {
    asm volatile("ldmatrix.sync.aligned.m8n8.x4.trans.shared.b16 {%0,%1,%2,%3}, [%4];"
                 : "=r"(r0), "=r"(r1), "=r"(r2), "=r"(r3) : "r"(addr));
}

__device__ __forceinline__ void cpa16(void* smemDst, const void* gsrc, int srcBytes) {
    uint32_t saddr = (uint32_t)__cvta_generic_to_shared(smemDst);
    asm volatile("cp.async.cg.shared.global [%0], [%1], 16, %2;\n"
                 :: "r"(saddr), "l"(gsrc), "r"(srcBytes));
}
__device__ __forceinline__ void cpa_commit() { asm volatile("cp.async.commit_group;\n"); }
__device__ __forceinline__ void cpa_wait2() { asm volatile("cp.async.wait_group 2;\n"); }
__device__ __forceinline__ void cpa_wait1() { asm volatile("cp.async.wait_group 1;\n"); }
__device__ __forceinline__ void cpa_wait0() { asm volatile("cp.async.wait_group 0;\n"); }

__device__ __forceinline__ uint32_t scale_h2(uint32_t u, float s) {
    __half2 hv = *reinterpret_cast<const __half2*>(&u);
    float2 f = __half22float2(hv);
    __half2 o = __floats2half2_rn(f.x * s, f.y * s);
    return *reinterpret_cast<uint32_t*>(&o);
}
__device__ __forceinline__ uint32_t pack_h2(float a, float b) {
    __half2 o = __floats2half2_rn(a, b);
    return *reinterpret_cast<uint32_t*>(&o);
}

// ---------------------------------------------------------------------------
// fp16 cp.async GEMM (R12-proven): CTA 128x64x32, 256 thr / 8 warps (4m x 2n),
// warp tile 32x32, ldmatrix frag loads, 4 stages, 2 CTAs/SM.
// C = [A | A2](half) x B^T(half) + epilogue.
// ---------------------------------------------------------------------------
#define GBM 128
#define GBN 64
#define KT 32
#define APH 40                         // halves per smem row (32 + 8 pad) = 80 B
#define STAGES 4
#define STAGE_H ((GBM + GBN) * APH)    // 7680 halves = 15360 B
#define GEMM_SMEM (STAGES * STAGE_H * 2)

__global__ void __launch_bounds__(256, 2) gemm_f16_kernel(
    int M, int N, int K,
    const __half* __restrict__ A, int lda,
    const __half* __restrict__ A2, int kSplit,
    const __half* __restrict__ B, int ldb,
    float* __restrict__ C, __half* __restrict__ Ch, int ldc,
    const float* __restrict__ bias,
    const float* __restrict__ biasScale,
    int relu,
    const float* __restrict__ addC,
    const float* __restrict__ rowMask)
{
    extern __shared__ __half smh[];

    const int bm = blockIdx.y * GBM;
    const int bn = blockIdx.x * GBN;
    const int t = threadIdx.x;
    const int lane = t & 31;
    const int wid = t >> 5;
    const int q = lane >> 2;
    const int r = lane & 3;
    const int grp = lane >> 3;
    const int lr = lane & 7;
    const int wm = (wid & 3) * 32;
    const int wn = (wid >> 2) * 32;

    float acc[2][4][4];
    #pragma unroll
    for (int mi = 0; mi < 2; mi++)
        #pragma unroll
        for (int ni = 0; ni < 4; ni++)
            #pragma unroll
            for (int e = 0; e < 4; e++) acc[mi][ni][e] = 0.0f;

    auto issueStage = [&](int buf, int k0) {
        __half* sA = smh + buf * STAGE_H;
        __half* sB = sA + GBM * APH;
        const __half* Asrc = (k0 < kSplit) ? A : A2;
        const int kk = (k0 < kSplit) ? k0 : (k0 - kSplit);
        #pragma unroll
        for (int i = 0; i < 2; i++) {
            int idx = t + 256 * i;
            int row = idx >> 2;
            int c8 = (idx & 3) * 8;
            int gm = bm + row;
            int ok = (gm < M);
            cpa16(sA + row * APH + c8,
                  Asrc + (long long)(ok ? gm : 0) * lda + kk + c8, ok ? 16 : 0);
        }
        {
            int row = t >> 2;
            int c8 = (t & 3) * 8;
            int gn = bn + row;
            int ok = (gn < N);
            cpa16(sB + row * APH + c8,
                  B + (long long)(ok ? gn : 0) * ldb + k0 + c8, ok ? 16 : 0);
        }
    };

    auto computeStage = [&](int buf) {
        const uint32_t sa = (uint32_t)__cvta_generic_to_shared(smh + buf * STAGE_H);
        const uint32_t sb = (uint32_t)__cvta_generic_to_shared(smh + buf * STAGE_H + GBM * APH);
        #pragma unroll
        for (int ks = 0; ks < 2; ks++) {
            const int kb = ks * 16;
            uint32_t af[2][4], bf[4][2];
            #pragma unroll
            for (int mi = 0; mi < 2; mi++) {
                int arow = wm + mi * 16 + ((grp & 1) ? 8 : 0) + lr;
                int acol = kb + ((grp & 2) ? 8 : 0);
                ldsm_x4(af[mi][0], af[mi][1], af[mi][2], af[mi][3],
                        sa + (arow * APH + acol) * 2);
            }
            #pragma unroll
            for (int nfp = 0; nfp < 2; nfp++) {
                int brow = wn + nfp * 16 + ((grp & 2) ? 8 : 0) + lr;
                int bcol = kb + ((grp & 1) ? 8 : 0);
                uint32_t b0, b1, b2, b3;
                ldsm_x4(b0, b1, b2, b3, sb + (brow * APH + bcol) * 2);
                bf[2 * nfp][0] = b0;      bf[2 * nfp][1] = b1;
                bf[2 * nfp + 1][0] = b2;  bf[2 * nfp + 1][1] = b3;
            }
            #pragma unroll
            for (int mi = 0; mi < 2; mi++)
                #pragma unroll
                for (int ni = 0; ni < 4; ni++)
                    mma_f16(acc[mi][ni], af[mi], bf[ni], acc[mi][ni]);
        }
    };

    const int ntiles = K / KT;
    #pragma unroll
    for (int s = 0; s < STAGES - 1; s++) {
        if (s < ntiles) issueStage(s, s * KT);
        cpa_commit();
    }
    for (int it = 0; it < ntiles; it++) {
        cpa_wait2();
        __syncthreads();
        const int nj = it + STAGES - 1;
        if (nj < ntiles) issueStage(nj & (STAGES - 1), nj * KT);
        cpa_commit();
        computeStage(it & (STAGES - 1));
    }

    // ---- epilogue ----
    #pragma unroll
    for (int mi = 0; mi < 2; mi++) {
        #pragma unroll
        for (int hh = 0; hh < 2; hh++) {
            int gm = bm + wm + mi * 16 + q + hh * 8;
            if (gm >= M) continue;
            float bs = biasScale ? biasScale[gm] : 1.0f;
            float rmv = rowMask ? rowMask[gm] : 1.0f;
            #pragma unroll
            for (int ni = 0; ni < 4; ni++) {
                int gn0 = bn + wn + ni * 8 + 2 * r;
                if (gn0 >= N) continue;
                float v[2];
                #pragma unroll
                for (int j = 0; j < 2; j++) {
                    int gn = gn0 + j;
                    float x = acc[mi][ni][hh * 2 + j];
                    if (bias && gn < N) x += bias[gn] * bs;
                    if (relu) x = fmaxf(x, 0.0f);
                    if (addC && gn < N) x += addC[(long long)gm * ldc + gn];
                    v[j] = x * rmv;
                }
                if (C) {
                    C[(long long)gm * ldc + gn0] = v[0];
                    if (gn0 + 1 < N) C[(long long)gm * ldc + gn0 + 1] = v[1];
                }
                if (Ch) {
                    *reinterpret_cast<__half2*>(Ch + (long long)gm * ldc + gn0) =
                        __floats2half2_rn(v[0], v[1]);
                }
            }
        }
    }
}

// ---------------------------------------------------------------------------
// fp16 flash attention, 128-row Q tile, 256 thr / 8 warps, double-buffered KV.
// CTA = 128 query rows x 1 head; KV tiles of 64. Per-warp code identical to
// the validated 64-row version (warp owns 16 Q rows).
// ---------------------------------------------------------------------------
#define FPITCH_H 136
#define FL_STAGE_H (2 * 64 * FPITCH_H)
#define FLASH_SMEM (2 * FL_STAGE_H * 2)

__global__ void __launch_bounds__(256) flash_f16_kernel(
    const __half* __restrict__ QKV, __half* __restrict__ O, int n)
{
    extern __shared__ __half fsm[];

    const int t = threadIdx.x;
    const int warp = t >> 5;          // 0..7
    const int lane = t & 31;
    const int q = lane >> 2;
    const int r = lane & 3;
    const int head = blockIdx.y;
    const int qbase = blockIdx.x * 128;
    const int row0 = warp * 16 + q;   // 0..127
    const float scale = 0.08838834764831845f;

    const uint32_t sbase = (uint32_t)__cvta_generic_to_shared(fsm);

    auto issueKV = [&](int kt, int buf) {
        __half* sK = fsm + buf * FL_STAGE_H;
        __half* sV = sK + 64 * FPITCH_H;
        #pragma unroll
        for (int i = 0; i < 4; i++) {
            int idx = t + 256 * i;
            int row = idx >> 4;
            int c8 = (idx & 15) * 8;
            const __half* kp = QKV + (long long)(kt * 64 + row) * (3 * CC) + CC + head * DH + c8;
            cpa16(sK + row * FPITCH_H + c8, kp, 16);
            cpa16(sV + row * FPITCH_H + c8, kp + CC, 16);
        }
    };

    uint32_t qf[8][4];
    {
        const __half* q0p = QKV + (long long)(qbase + row0) * (3 * CC) + head * DH;
        const __half* q1p = q0p + 8LL * (3 * CC);
        #pragma unroll
        for (int kc = 0; kc < 8; kc++) {
            qf[kc][0] = scale_h2(*(const uint32_t*)(q0p + kc * 16 + 2 * r), scale);
            qf[kc][1] = scale_h2(*(const uint32_t*)(q1p + kc * 16 + 2 * r), scale);
            qf[kc][2] = scale_h2(*(const uint32_t*)(q0p + kc * 16 + 2 * r + 8), scale);
            qf[kc][3] = scale_h2(*(const uint32_t*)(q1p + kc * 16 + 2 * r + 8), scale);
        }
    }

    float oacc[16][4];
    #pragma unroll
    for (int df = 0; df < 16; df++)
        #pragma unroll
        for (int e = 0; e < 4; e++) oacc[df][e] = 0.0f;
    float m0 = -1e30f, m1 = -1e30f, l0 = 0.0f, l1 = 0.0f;

    const int grp = lane >> 3;
    const int lr = lane & 7;

    const int ntiles = n / 64;
    issueKV(0, 0);
    cpa_commit();

    for (int kt = 0; kt < ntiles; kt++) {
        if (kt + 1 < ntiles) {
            issueKV(kt + 1, (kt + 1) & 1);
            cpa_commit();
            cpa_wait1();
        } else {
            cpa_wait0();
        }
        __syncthreads();

        const uint32_t skb = sbase + ((kt & 1) * FL_STAGE_H) * 2;
        const uint32_t svb = skb + 64 * FPITCH_H * 2;

        float sacc[8][4];
        #pragma unroll
        for (int nf = 0; nf < 8; nf++)
            #pragma unroll
            for (int e = 0; e < 4; e++) sacc[nf][e] = 0.0f;
        #pragma unroll
        for (int kc = 0; kc < 8; kc++) {
            #pragma unroll
            for (int nfp = 0; nfp < 4; nfp++) {
                int kvr = nfp * 16 + ((grp & 2) ? 8 : 0) + lr;
                int dc = kc * 16 + ((grp & 1) ? 8 : 0);
                uint32_t b0, b1, b2, b3;
                ldsm_x4(b0, b1, b2, b3, skb + (kvr * FPITCH_H + dc) * 2);
                uint32_t bA[2] = {b0, b1}, bB[2] = {b2, b3};
                mma_f16(sacc[2 * nfp], qf[kc], bA, sacc[2 * nfp]);
                mma_f16(sacc[2 * nfp + 1], qf[kc], bB, sacc[2 * nfp + 1]);
            }
        }

        float tm0 = -1e30f, tm1 = -1e30f;
        #pragma unroll
        for (int nf = 0; nf < 8; nf++) {
            tm0 = fmaxf(tm0, fmaxf(sacc[nf][0], sacc[nf][1]));
            tm1 = fmaxf(tm1, fmaxf(sacc[nf][2], sacc[nf][3]));
        }
        tm0 = fmaxf(tm0, __shfl_xor_sync(0xffffffffu, tm0, 1));
        tm0 = fmaxf(tm0, __shfl_xor_sync(0xffffffffu, tm0, 2));
        tm1 = fmaxf(tm1, __shfl_xor_sync(0xffffffffu, tm1, 1));
        tm1 = fmaxf(tm1, __shfl_xor_sync(0xffffffffu, tm1, 2));
        const float nm0 = fmaxf(m0, tm0);
        const float nm1 = fmaxf(m1, tm1);
        const float cor0 = __expf(m0 - nm0);
        const float cor1 = __expf(m1 - nm1);
        m0 = nm0; m1 = nm1;

        float ts0 = 0.0f, ts1 = 0.0f;
        #pragma unroll
        for (int nf = 0; nf < 8; nf++) {
            sacc[nf][0] = __expf(sacc[nf][0] - m0);
            sacc[nf][1] = __expf(sacc[nf][1] - m0);
            sacc[nf][2] = __expf(sacc[nf][2] - m1);
            sacc[nf][3] = __expf(sacc[nf][3] - m1);
            ts0 += sacc[nf][0] + sacc[nf][1];
            ts1 += sacc[nf][2] + sacc[nf][3];
        }
        ts0 += __shfl_xor_sync(0xffffffffu, ts0, 1);
        ts0 += __shfl_xor_sync(0xffffffffu, ts0, 2);
        ts1 += __shfl_xor_sync(0xffffffffu, ts1, 1);
        ts1 += __shfl_xor_sync(0xffffffffu, ts1, 2);
        l0 = l0 * cor0 + ts0;
        l1 = l1 * cor1 + ts1;

        uint32_t pf[4][4];
        #pragma unroll
        for (int j = 0; j < 4; j++) {
            pf[j][0] = pack_h2(sacc[2 * j][0], sacc[2 * j][1]);
            pf[j][1] = pack_h2(sacc[2 * j][2], sacc[2 * j][3]);
            pf[j][2] = pack_h2(sacc[2 * j + 1][0], sacc[2 * j + 1][1]);
            pf[j][3] = pack_h2(sacc[2 * j + 1][2], sacc[2 * j + 1][3]);
        }

        #pragma unroll
        for (int df = 0; df < 16; df++) {
            oacc[df][0] *= cor0; oacc[df][1] *= cor0;
            oacc[df][2] *= cor1; oacc[df][3] *= cor1;
        }

        #pragma unroll
        for (int j = 0; j < 4; j++) {
            #pragma unroll
            for (int dfp = 0; dfp < 8; dfp++) {
                int kvr = 16 * j + ((grp & 1) ? 8 : 0) + lr;
                int dc = dfp * 16 + ((grp & 2) ? 8 : 0);
                uint32_t b0, b1, b2, b3;
                ldsm_x4_t(b0, b1, b2, b3, svb + (kvr * FPITCH_H + dc) * 2);
                uint32_t bA[2] = {b0, b1}, bB[2] = {b2, b3};
                mma_f16(oacc[2 * dfp], pf[j], bA, oacc[2 * dfp]);
                mma_f16(oacc[2 * dfp + 1], pf[j], bB, oacc[2 * dfp + 1]);
            }
        }
        __syncthreads();
    }

    const float inv0 = 1.0f / l0;
    const float inv1 = 1.0f / l1;
    #pragma unroll
    for (int df = 0; df < 16; df++) {
        const int gc = head * DH + df * 8 + 2 * r;
        *reinterpret_cast<__half2*>(O + (long long)(qbase + row0) * CC + gc) =
            __floats2half2_rn(oacc[df][0] * inv0, oacc[df][1] * inv0);
        *reinterpret_cast<__half2*>(O + (long long)(qbase + row0 + 8) * CC + gc) =
            __floats2half2_rn(oacc[df][2] * inv1, oacc[df][3] * inv1);
    }
}

// ---------------------------------------------------------------------------
// Block reduction (128 threads, 4 warps)
// ---------------------------------------------------------------------------
__device__ __forceinline__ float blockReduceSum128(float v, float* red) {
    #pragma unroll
    for (int o = 16; o > 0; o >>= 1) v += __shfl_xor_sync(0xffffffffu, v, o);
    int w = threadIdx.x >> 5;
    if ((threadIdx.x & 31) == 0) red[w] = v;
    __syncthreads();
    float rr;
    if (threadIdx.x < 32) {
        rr = (threadIdx.x < 4) ? red[threadIdx.x] : 0.0f;
        #pragma unroll
        for (int o = 2; o > 0; o >>= 1) rr += __shfl_xor_sync(0xffffffffu, rr, o);
        if (threadIdx.x == 0) red[0] = rr;
    }
    __syncthreads();
    rr = red[0];
    __syncthreads();
    return rr;
}

// ---------------------------------------------------------------------------
// LN(a+b)*g+beta -> fp32 out + half out. 128 threads, float4-vectorized.
// ---------------------------------------------------------------------------
__global__ void add_ln_kernel(const float* __restrict__ a, const float* __restrict__ b,
                              const float* __restrict__ g, const float* __restrict__ be,
                              float* __restrict__ out, __half* __restrict__ outH)
{
    long long row = blockIdx.x;
    const float4* a4 = (const float4*)(a + row * CC);
    const float4* b4 = (const float4*)(b + row * CC);
    int tid = threadIdx.x;

    float4 av = a4[tid];
    float4 bv = b4[tid];
    float4 x;
    x.x = av.x + bv.x; x.y = av.y + bv.y; x.z = av.z + bv.z; x.w = av.w + bv.w;

    __shared__ float red[4];
    float mu = blockReduceSum128(x.x + x.y + x.z + x.w, red) * (1.0f / CC);
    float dx = x.x - mu, dy = x.y - mu, dz = x.z - mu, dw = x.w - mu;
    float var = blockReduceSum128(dx * dx + dy * dy + dz * dz + dw * dw, red) * (1.0f / CC);
    float rstd = rsqrtf(var + 1e-5f);

    const float4 gv = ((const float4*)g)[tid];
    const float4 bev = ((const float4*)be)[tid];
    float4 y;
    y.x = dx * rstd * gv.x + bev.x;
    y.y = dy * rstd * gv.y + bev.y;
    y.z = dz * rstd * gv.z + bev.z;
    y.w = dw * rstd * gv.w + bev.w;

    ((float4*)(out + row * CC))[tid] = y;
    __half2 h0 = __floats2half2_rn(y.x, y.y);
    __half2 h1 = __floats2half2_rn(y.z, y.w);
    uint2 ho;
    ho.x = *reinterpret_cast<uint32_t*>(&h0);
    ho.y = *reinterpret_cast<uint32_t*>(&h1);
    ((uint2*)(outH + row * CC))[tid] = ho;
}

// ---------------------------------------------------------------------------
// Masked-mean aggregation, vectorized float4 -> half2 out (+ optional coef)
// ---------------------------------------------------------------------------
__global__ void agg_kernel(const float* __restrict__ X, int C,
                           const int* __restrict__ nbm,
                           const float* __restrict__ childMask,
                           __half* __restrict__ out, float* __restrict__ coefOut, int P)
{
    int C4 = C >> 2;
    long long idx = (long long)blockIdx.x * blockDim.x + threadIdx.x;
    if (idx >= (long long)P * C4) return;
    int p = (int)(idx / C4);
    int c4 = (int)(idx % C4);
    const float4* X4 = (const float4*)X;
    float4 sum = make_float4(0.f, 0.f, 0.f, 0.f);
    float den = 0.0f, wsum = 0.0f;
    #pragma unroll
    for (int f = 0; f < FAN; f++) {
        float nb = (float)nbm[p * FAN + f];
        den += nb;
        float w = nb * (childMask ? childMask[p * FAN + f] : 1.0f);
        wsum += w;
        float4 v = X4[(long long)(p * FAN + f) * C4 + c4];
        sum.x += w * v.x; sum.y += w * v.y; sum.z += w * v.z; sum.w += w * v.w;
    }
    den = fmaxf(den, 1.0f);
    float inv = 1.0f / den;
    __half2 a = __floats2half2_rn(sum.x * inv, sum.y * inv);
    __half2 b = __floats2half2_rn(sum.z * inv, sum.w * inv);
    uint2 o;
    o.x = *reinterpret_cast<uint32_t*>(&a);
    o.y = *reinterpret_cast<uint32_t*>(&b);
    ((uint2*)out)[(long long)p * C4 + c4] = o;
    if (coefOut && c4 == 0) coefOut[p] = wsum * inv;
}

// ---------------------------------------------------------------------------
// Multi-segment vectorized fp32 -> fp16 conversion
// ---------------------------------------------------------------------------
#define MAXSEG 12
struct CvtJobs {
    const float* src[MAXSEG];
    __half* dst[MAXSEG];
    int quads[MAXSEG];
    int nseg;
};

__global__ void cvt_multi_kernel(CvtJobs jobs)
{
    int seg = blockIdx.y;
    if (seg >= jobs.nseg) return;
    const float4* src = (const float4*)jobs.src[seg];
    uint2* dst = (uint2*)jobs.dst[seg];
    int nq = jobs.quads[seg];
    for (int i = blockIdx.x * blockDim.x + threadIdx.x; i < nq; i += gridDim.x * blockDim.x) {
        float4 v = src[i];
        __half2 a = __floats2half2_rn(v.x, v.y);
        __half2 b = __floats2half2_rn(v.z, v.w);
        uint2 o;
        o.x = *reinterpret_cast<uint32_t*>(&a);
        o.y = *reinterpret_cast<uint32_t*>(&b);
        dst[i] = o;
    }
}

// ---------------------------------------------------------------------------
// Host orchestration
// ---------------------------------------------------------------------------
static void gemm(int M, int N, int K,
                 const __half* A, int lda, const __half* A2, int kSplit,
                 const __half* B, int ldb,
                 float* C, __half* Ch, int ldc,
                 const float* bias, const float* biasScale, int relu,
                 const float* addC, const float* rowMask)
{
    dim3 grid((N + GBN - 1) / GBN, (M + GBM - 1) / GBM);
    gemm_f16_kernel<<<grid, 256, GEMM_SMEM>>>(
        M, N, K, A, lda, A2, kSplit, B, ldb, C, Ch, ldc,
        bias, biasScale, relu, addC, rowMask);
}

struct Scratch {
    float *S1E, *S1N, *S0, *AGGC, *HL, *H1, *ATT, *H2;
    __half *S1Eh, *S0h, *AGGFh, *AGGh, *H1h, *QKVh, *ATTOh, *H2h, *FF1h;
    __half *embWh, *sageWh, *qkvWh, *outWh, *ffnW1h, *ffnW2h, *clsWh, *feats0h, *feats1h;
};

static Scratch get_scratch() {
    Scratch s; void* p;
    cudaGetSymbolAddress(&p, g_S1E);    s.S1E    = (float*)p;
    cudaGetSymbolAddress(&p, g_S1N);    s.S1N    = (float*)p;
    cudaGetSymbolAddress(&p, g_S0);     s.S0     = (float*)p;
    cudaGetSymbolAddress(&p, g_AGGC);   s.AGGC   = (float*)p;
    cudaGetSymbolAddress(&p, g_HL);     s.HL     = (float*)p;
    cudaGetSymbolAddress(&p, g_H1);     s.H1     = (float*)p;
    cudaGetSymbolAddress(&p, g_ATT);    s.ATT    = (float*)p;
    cudaGetSymbolAddress(&p, g_H2);     s.H2     = (float*)p;
    cudaGetSymbolAddress(&p, g_S1Eh);   s.S1Eh   = (__half*)p;
    cudaGetSymbolAddress(&p, g_S0h);    s.S0h    = (__half*)p;
    cudaGetSymbolAddress(&p, g_AGGFh);  s.AGGFh  = (__half*)p;
    cudaGetSymbolAddress(&p, g_AGGh);   s.AGGh   = (__half*)p;
    cudaGetSymbolAddress(&p, g_H1h);    s.H1h    = (__half*)p;
    cudaGetSymbolAddress(&p, g_QKVh);   s.QKVh   = (__half*)p;
    cudaGetSymbolAddress(&p, g_ATTOh);  s.ATTOh  = (__half*)p;
    cudaGetSymbolAddress(&p, g_H2h);    s.H2h    = (__half*)p;
    cudaGetSymbolAddress(&p, g_FF1h);   s.FF1h   = (__half*)p;
    cudaGetSymbolAddress(&p, g_embWh);  s.embWh  = (__half*)p;
    cudaGetSymbolAddress(&p, g_sageWh); s.sageWh = (__half*)p;
    cudaGetSymbolAddress(&p, g_qkvWh);  s.qkvWh  = (__half*)p;
    cudaGetSymbolAddress(&p, g_outWh);  s.outWh  = (__half*)p;
    cudaGetSymbolAddress(&p, g_ffnW1h); s.ffnW1h = (__half*)p;
    cudaGetSymbolAddress(&p, g_ffnW2h); s.ffnW2h = (__half*)p;
    cudaGetSymbolAddress(&p, g_clsWh);  s.clsWh  = (__half*)p;
    cudaGetSymbolAddress(&p, g_feats0h); s.feats0h = (__half*)p;
    cudaGetSymbolAddress(&p, g_feats1h); s.feats1h = (__half*)p;
    return s;
}

struct LayerW {
    const __half *sageW, *qkvW, *outW, *ffnW1, *ffnW2;
    const float *sageB, *qkvB, *outB, *ffnB1, *ffnB2;
    const float *n1g, *n1b, *n2g, *n2b;
};

static void block_forward(int n, const float* sf, const __half* sfh, const __half* agg,
                          float* outState, __half* outStateH,
                          const float* rowMask, const LayerW& w, const Scratch& s)
{
    gemm(n, CC, 2 * CC, sfh, CC, agg, CC, w.sageW, 2 * CC,
         s.HL, nullptr, CC, w.sageB, nullptr, 0, nullptr, nullptr);
    add_ln_kernel<<<n, 128>>>(sf, s.HL, w.n1g, w.n1b, s.H1, s.H1h);

    gemm(n, 3 * CC, CC, s.H1h, CC, nullptr, CC, w.qkvW, CC,
         nullptr, s.QKVh, 3 * CC, w.qkvB, nullptr, 0, nullptr, nullptr);

    {
        dim3 grid(n / 128, HH);
        flash_f16_kernel<<<grid, 256, FLASH_SMEM>>>(s.QKVh, s.ATTOh, n);
    }

    gemm(n, CC, CC, s.ATTOh, CC, nullptr, CC, w.outW, CC,
         s.ATT, nullptr, CC, w.outB, nullptr, 0, nullptr, nullptr);
    add_ln_kernel<<<n, 128>>>(s.H1, s.ATT, w.n2g, w.n2b, s.H2, s.H2h);

    gemm(n, 2 * CC, CC, s.H2h, CC, nullptr, CC, w.ffnW1, CC,
         nullptr, s.FF1h, 2 * CC, w.ffnB1, nullptr, 1, nullptr, nullptr);
    gemm(n, CC, 2 * CC, s.FF1h, 2 * CC, nullptr, 2 * CC, w.ffnW2, 2 * CC,
         outState, outStateH, CC, w.ffnB2, nullptr, 0, s.H2, rowMask);
}

extern "C" void kernel_launch(void* const* d_in, const int* in_sizes, int n_in,
                              void* d_out, int out_size)
{
    const float* feats0  = (const float*)d_in[0];
    const float* feats1  = (const float*)d_in[1];
    const float* feats2  = (const float*)d_in[2];
    const float* nmask0  = (const float*)d_in[3];
    const float* nmask1  = (const float*)d_in[4];
    const float* nmask2  = (const float*)d_in[5];
    const int*   nbmask0 = (const int*)d_in[6];
    const int*   nbmask1 = (const int*)d_in[7];
    const float* emb_w   = (const float*)d_in[8];
    const float* emb_b   = (const float*)d_in[9];
    const float* sage_w  = (const float*)d_in[10];
    const float* sage_b  = (const float*)d_in[11];
    const float* qkv_w   = (const float*)d_in[12];
    const float* qkv_b   = (const float*)d_in[13];
    const float* out_w   = (const float*)d_in[14];
    const float* out_b   = (const float*)d_in[15];
    const float* n1_g    = (const float*)d_in[16];
    const float* n1_b    = (const float*)d_in[17];
    const float* n2_g    = (const float*)d_in[18];
    const float* n2_b    = (const float*)d_in[19];
    const float* ffn_w1  = (const float*)d_in[20];
    const float* ffn_b1  = (const float*)d_in[21];
    const float* ffn_w2  = (const float*)d_in[22];
    const float* ffn_b2  = (const float*)d_in[23];
    const float* cls_w   = (const float*)d_in[24];
    const float* cls_b   = (const float*)d_in[25];
    float* out = (float*)d_out;

    cudaFuncSetAttribute(gemm_f16_kernel, cudaFuncAttributeMaxDynamicSharedMemorySize,
                         GEMM_SMEM);
    cudaFuncSetAttribute(flash_f16_kernel, cudaFuncAttributeMaxDynamicSharedMemorySize,
                         FLASH_SMEM);

    Scratch s = get_scratch();

    // ---- all fp32->fp16 conversions in one vectorized launch ----
    {
        CvtJobs j;
        j.src[0] = emb_w;   j.dst[0] = s.embWh;   j.quads[0] = CC * INDIM / 4;
        j.src[1] = sage_w;  j.dst[1] = s.sageWh;  j.quads[1] = NL * CC * 2 * CC / 4;
        j.src[2] = qkv_w;   j.dst[2] = s.qkvWh;   j.quads[2] = NL * 3 * CC * CC / 4;
        j.src[3] = out_w;   j.dst[3] = s.outWh;   j.quads[3] = NL * CC * CC / 4;
        j.src[4] = ffn_w1;  j.dst[4] = s.ffnW1h;  j.quads[4] = NL * 2 * CC * CC / 4;
        j.src[5] = ffn_w2;  j.dst[5] = s.ffnW2h;  j.quads[5] = NL * CC * 2 * CC / 4;
        j.src[6] = cls_w;   j.dst[6] = s.clsWh;   j.quads[6] = NC * CC / 4;
        j.src[7] = feats0;  j.dst[7] = s.feats0h; j.quads[7] = N0 * INDIM / 4;
        j.src[8] = feats1;  j.dst[8] = s.feats1h; j.quads[8] = N1 * INDIM / 4;
        j.nseg = 9;
        for (int i = j.nseg; i < MAXSEG; i++) { j.src[i] = nullptr; j.dst[i] = nullptr; j.quads[i] = 0; }
        dim3 grid(128, j.nseg);
        cvt_multi_kernel<<<grid, 256>>>(j);
    }

    LayerW w[NL];
    for (int li = 0; li < NL; li++) {
        w[li].sageW = s.sageWh + (long long)li * CC * 2 * CC;
        w[li].qkvW  = s.qkvWh  + (long long)li * 3 * CC * CC;
        w[li].outW  = s.outWh  + (long long)li * CC * CC;
        w[li].ffnW1 = s.ffnW1h + (long long)li * 2 * CC * CC;
        w[li].ffnW2 = s.ffnW2h + (long long)li * CC * 2 * CC;
        w[li].sageB = sage_b + li * CC;
        w[li].qkvB  = qkv_b  + li * 3 * CC;
        w[li].outB  = out_b  + li * CC;
        w[li].ffnB1 = ffn_b1 + li * 2 * CC;
        w[li].ffnB2 = ffn_b2 + li * CC;
        w[li].n1g = n1_g + li * CC;  w[li].n1b = n1_b + li * CC;
        w[li].n2g = n2_g + li * CC;  w[li].n2b = n2_b + li * CC;
    }

    // ---- embeddings (depth 0, 1), masked; write fp32 + half ----
    gemm(N0, CC, INDIM, s.feats0h, INDIM, nullptr, INDIM, s.embWh, INDIM,
         s.S0, s.S0h, CC, emb_b, nullptr, 0, nullptr, nmask0);
    gemm(N1, CC, INDIM, s.feats1h, INDIM, nullptr, INDIM, s.embWh, INDIM,
         s.S1E, s.S1Eh, CC, emb_b, nullptr, 0, nullptr, nmask1);

    // ---- depth-2: aggregate RAW feats2 then one embedding GEMM ----
    agg_kernel<<<(int)(((long long)N1 * INDIM / 4 + 255) / 256), 256>>>(
        feats2, INDIM, nbmask1, nmask2, s.AGGFh, s.AGGC, N1);
    gemm(N1, CC, INDIM, s.AGGFh, INDIM, nullptr, INDIM, s.embWh, INDIM,
         nullptr, s.AGGh, CC, emb_b, s.AGGC, 0, nullptr, nullptr);

    // ---- layer 0, depth 1 (n=4096) ----
    block_forward(N1, s.S1E, s.S1Eh, s.AGGh, s.S1N, nullptr, nmask1, w[0], s);

    // ---- layer 0, depth 0 ----
    agg_kernel<<<(int)(((long long)N0 * CC / 4 + 255) / 256), 256>>>(
        s.S1E, CC, nbmask0, nullptr, s.AGGh, nullptr, N0);
    block_forward(N0, s.S0, s.S0h, s.AGGh, s.S0, s.S0h, nmask0, w[0], s);

    // ---- layer 1, depth 0 ----
    agg_kernel<<<(int)(((long long)N0 * CC / 4 + 255) / 256), 256>>>(
        s.S1N, CC, nbmask0, nullptr, s.AGGh, nullptr, N0);
    block_forward(N0, s.S0, s.S0h, s.AGGh, s.S0, s.S0h, nmask0, w[1], s);

    // ---- classifier ----
    gemm(N0, NC, CC, s.S0h, CC, nullptr, CC, s.clsWh, CC,
         out, nullptr, NC, cls_b, nullptr, 0, nullptr, nullptr);
}

// round 16
// speedup vs baseline: 1.3802x; 1.2097x over previous
#include <cuda_runtime.h>
#include <cuda_fp16.h>
#include <math.h>
#include <stdint.h>

// ---------------------------------------------------------------------------
// Problem constants
// ---------------------------------------------------------------------------
#define NL 2
#define HH 4
#define CC 512
#define INDIM 256
#define FAN 16
#define NC 47
#define DH 128
#define N0 256
#define N1 4096

// ---------------------------------------------------------------------------
// Device scratch (fp32 + half mirrors)
// ---------------------------------------------------------------------------
__device__ float g_S1E[N1 * CC];
__device__ float g_S1N[N1 * CC];
__device__ float g_S0[N0 * CC];
__device__ float g_AGGC[N1];
__device__ float g_HL[N1 * CC];
__device__ float g_H1[N1 * CC];
__device__ float g_ATT[N1 * CC];
__device__ float g_H2[N1 * CC];

__device__ __half g_S1Eh[N1 * CC];
__device__ __half g_S0h[N0 * CC];
__device__ __half g_AGGFh[N1 * INDIM];
__device__ __half g_AGGh[N1 * CC];
__device__ __half g_H1h[N1 * CC];
__device__ __half g_QKVh[N1 * 3 * CC];
__device__ __half g_ATTOh[N1 * CC];
__device__ __half g_H2h[N1 * CC];
__device__ __half g_FF1h[N1 * 2 * CC];

// small-block (N0) dedicated scratch for concurrent stream
__device__ float g_HL0[N0 * CC];
__device__ float g_H10[N0 * CC];
__device__ float g_ATT0[N0 * CC];
__device__ float g_H20[N0 * CC];
__device__ __half g_H1h0[N0 * CC];
__device__ __half g_QKVh0[N0 * 3 * CC];
__device__ __half g_ATTOh0[N0 * CC];
__device__ __half g_H2h0[N0 * CC];
__device__ __half g_FF1h0[N0 * 2 * CC];
__device__ __half g_AGGh0[N0 * CC];

// half weights
__device__ __half g_embWh[CC * INDIM];
__device__ __half g_sageWh[NL * CC * 2 * CC];
__device__ __half g_qkvWh[NL * 3 * CC * CC];
__device__ __half g_outWh[NL * CC * CC];
__device__ __half g_ffnW1h[NL * 2 * CC * CC];
__device__ __half g_ffnW2h[NL * CC * 2 * CC];
__device__ __half g_clsWh[NC * CC];
__device__ __half g_feats0h[N0 * INDIM];
__device__ __half g_feats1h[N1 * INDIM];

// ---------------------------------------------------------------------------
// helpers
// ---------------------------------------------------------------------------
__device__ __forceinline__ void mma_f16(float* d, const uint32_t* a, const uint32_t* b,
                                        const float* c) {
    asm volatile(
        "mma.sync.aligned.m16n8k16.row.col.f32.f16.f16.f32 "
        "{%0,%1,%2,%3}, {%4,%5,%6,%7}, {%8,%9}, {%10,%11,%12,%13};\n"
        : "=f"(d[0]), "=f"(d[1]), "=f"(d[2]), "=f"(d[3])
        : "r"(a[0]), "r"(a[1]), "r"(a[2]), "r"(a[3]),
          "r"(b[0]), "r"(b[1]),
          "f"(c[0]), "f"(c[1]), "f"(c[2]), "f"(c[3]));
}

__device__ __forceinline__ void ldsm_x4(uint32_t& r0, uint32_t& r1, uint32_t& r2,
                                        uint32_t& r3, uint32_t addr) {
    asm volatile("ldmatrix.sync.aligned.m8n8.x4.shared.b16 {%0,%1,%2,%3}, [%4];"
                 : "=r"(r0), "=r"(r1), "=r"(r2), "=r"(r3) : "r"(addr));
}
__device__ __forceinline__ void ldsm_x4_t(uint32_t& r0, uint32_t& r1, uint32_t& r2,
                                          uint32_t& r3, uint32_t addr) {
    asm volatile("ldmatrix.sync.aligned.m8n8.x4.trans.shared.b16 {%0,%1,%2,%3}, [%4];"
                 : "=r"(r0), "=r"(r1), "=r"(r2), "=r"(r3) : "r"(addr));
}

__device__ __forceinline__ void cpa16(void* smemDst, const void* gsrc, int srcBytes) {
    uint32_t saddr = (uint32_t)__cvta_generic_to_shared(smemDst);
    asm volatile("cp.async.cg.shared.global [%0], [%1], 16, %2;\n"
                 :: "r"(saddr), "l"(gsrc), "r"(srcBytes));
}
__device__ __forceinline__ void cpa_commit() { asm volatile("cp.async.commit_group;\n"); }
__device__ __forceinline__ void cpa_wait2() { asm volatile("cp.async.wait_group 2;\n"); }
__device__ __forceinline__ void cpa_wait1() { asm volatile("cp.async.wait_group 1;\n"); }
__device__ __forceinline__ void cpa_wait0() { asm volatile("cp.async.wait_group 0;\n"); }

__device__ __forceinline__ uint32_t scale_h2(uint32_t u, float s) {
    __half2 hv = *reinterpret_cast<const __half2*>(&u);
    float2 f = __half22float2(hv);
    __half2 o = __floats2half2_rn(f.x * s, f.y * s);
    return *reinterpret_cast<uint32_t*>(&o);
}
__device__ __forceinline__ uint32_t pack_h2(float a, float b) {
    __half2 o = __floats2half2_rn(a, b);
    return *reinterpret_cast<uint32_t*>(&o);
}

// ---------------------------------------------------------------------------
// fp16 cp.async GEMM (R12-proven): CTA 128x64x32, 256 thr / 8 warps (4m x 2n),
// warp tile 32x32, ldmatrix frag loads, 4 stages, 2 CTAs/SM.
// ---------------------------------------------------------------------------
#define GBM 128
#define GBN 64
#define KT 32
#define APH 40
#define STAGES 4
#define STAGE_H ((GBM + GBN) * APH)
#define GEMM_SMEM (STAGES * STAGE_H * 2)

__global__ void __launch_bounds__(256, 2) gemm_f16_kernel(
    int M, int N, int K,
    const __half* __restrict__ A, int lda,
    const __half* __restrict__ A2, int kSplit,
    const __half* __restrict__ B, int ldb,
    float* __restrict__ C, __half* __restrict__ Ch, int ldc,
    const float* __restrict__ bias,
    const float* __restrict__ biasScale,
    int relu,
    const float* __restrict__ addC,
    const float* __restrict__ rowMask)
{
    extern __shared__ __half smh[];

    const int bm = blockIdx.y * GBM;
    const int bn = blockIdx.x * GBN;
    const int t = threadIdx.x;
    const int lane = t & 31;
    const int wid = t >> 5;
    const int q = lane >> 2;
    const int r = lane & 3;
    const int grp = lane >> 3;
    const int lr = lane & 7;
    const int wm = (wid & 3) * 32;
    const int wn = (wid >> 2) * 32;

    float acc[2][4][4];
    #pragma unroll
    for (int mi = 0; mi < 2; mi++)
        #pragma unroll
        for (int ni = 0; ni < 4; ni++)
            #pragma unroll
            for (int e = 0; e < 4; e++) acc[mi][ni][e] = 0.0f;

    auto issueStage = [&](int buf, int k0) {
        __half* sA = smh + buf * STAGE_H;
        __half* sB = sA + GBM * APH;
        const __half* Asrc = (k0 < kSplit) ? A : A2;
        const int kk = (k0 < kSplit) ? k0 : (k0 - kSplit);
        #pragma unroll
        for (int i = 0; i < 2; i++) {
            int idx = t + 256 * i;
            int row = idx >> 2;
            int c8 = (idx & 3) * 8;
            int gm = bm + row;
            int ok = (gm < M);
            cpa16(sA + row * APH + c8,
                  Asrc + (long long)(ok ? gm : 0) * lda + kk + c8, ok ? 16 : 0);
        }
        {
            int row = t >> 2;
            int c8 = (t & 3) * 8;
            int gn = bn + row;
            int ok = (gn < N);
            cpa16(sB + row * APH + c8,
                  B + (long long)(ok ? gn : 0) * ldb + k0 + c8, ok ? 16 : 0);
        }
    };

    auto computeStage = [&](int buf) {
        const uint32_t sa = (uint32_t)__cvta_generic_to_shared(smh + buf * STAGE_H);
        const uint32_t sb = (uint32_t)__cvta_generic_to_shared(smh + buf * STAGE_H + GBM * APH);
        #pragma unroll
        for (int ks = 0; ks < 2; ks++) {
            const int kb = ks * 16;
            uint32_t af[2][4], bf[4][2];
            #pragma unroll
            for (int mi = 0; mi < 2; mi++) {
                int arow = wm + mi * 16 + ((grp & 1) ? 8 : 0) + lr;
                int acol = kb + ((grp & 2) ? 8 : 0);
                ldsm_x4(af[mi][0], af[mi][1], af[mi][2], af[mi][3],
                        sa + (arow * APH + acol) * 2);
            }
            #pragma unroll
            for (int nfp = 0; nfp < 2; nfp++) {
                int brow = wn + nfp * 16 + ((grp & 2) ? 8 : 0) + lr;
                int bcol = kb + ((grp & 1) ? 8 : 0);
                uint32_t b0, b1, b2, b3;
                ldsm_x4(b0, b1, b2, b3, sb + (brow * APH + bcol) * 2);
                bf[2 * nfp][0] = b0;      bf[2 * nfp][1] = b1;
                bf[2 * nfp + 1][0] = b2;  bf[2 * nfp + 1][1] = b3;
            }
            #pragma unroll
            for (int mi = 0; mi < 2; mi++)
                #pragma unroll
                for (int ni = 0; ni < 4; ni++)
                    mma_f16(acc[mi][ni], af[mi], bf[ni], acc[mi][ni]);
        }
    };

    const int ntiles = K / KT;
    #pragma unroll
    for (int s = 0; s < STAGES - 1; s++) {
        if (s < ntiles) issueStage(s, s * KT);
        cpa_commit();
    }
    for (int it = 0; it < ntiles; it++) {
        cpa_wait2();
        __syncthreads();
        const int nj = it + STAGES - 1;
        if (nj < ntiles) issueStage(nj & (STAGES - 1), nj * KT);
        cpa_commit();
        computeStage(it & (STAGES - 1));
    }

    #pragma unroll
    for (int mi = 0; mi < 2; mi++) {
        #pragma unroll
        for (int hh = 0; hh < 2; hh++) {
            int gm = bm + wm + mi * 16 + q + hh * 8;
            if (gm >= M) continue;
            float bs = biasScale ? biasScale[gm] : 1.0f;
            float rmv = rowMask ? rowMask[gm] : 1.0f;
            #pragma unroll
            for (int ni = 0; ni < 4; ni++) {
                int gn0 = bn + wn + ni * 8 + 2 * r;
                if (gn0 >= N) continue;
                float v[2];
                #pragma unroll
                for (int j = 0; j < 2; j++) {
                    int gn = gn0 + j;
                    float x = acc[mi][ni][hh * 2 + j];
                    if (bias && gn < N) x += bias[gn] * bs;
                    if (relu) x = fmaxf(x, 0.0f);
                    if (addC && gn < N) x += addC[(long long)gm * ldc + gn];
                    v[j] = x * rmv;
                }
                if (C) {
                    C[(long long)gm * ldc + gn0] = v[0];
                    if (gn0 + 1 < N) C[(long long)gm * ldc + gn0 + 1] = v[1];
                }
                if (Ch) {
                    *reinterpret_cast<__half2*>(Ch + (long long)gm * ldc + gn0) =
                        __floats2half2_rn(v[0], v[1]);
                }
            }
        }
    }
}

// ---------------------------------------------------------------------------
// fp16 flash attention, 128-row Q tile, 256 thr / 8 warps, double-buffered KV.
// ---------------------------------------------------------------------------
#define FPITCH_H 136
#define FL_STAGE_H (2 * 64 * FPITCH_H)
#define FLASH_SMEM (2 * FL_STAGE_H * 2)

__global__ void __launch_bounds__(256) flash_f16_kernel(
    const __half* __restrict__ QKV, __half* __restrict__ O, int n)
{
    extern __shared__ __half fsm[];

    const int t = threadIdx.x;
    const int warp = t >> 5;
    const int lane = t & 31;
    const int q = lane >> 2;
    const int r = lane & 3;
    const int head = blockIdx.y;
    const int qbase = blockIdx.x * 128;
    const int row0 = warp * 16 + q;
    const float scale = 0.08838834764831845f;

    const uint32_t sbase = (uint32_t)__cvta_generic_to_shared(fsm);

    auto issueKV = [&](int kt, int buf) {
        __half* sK = fsm + buf * FL_STAGE_H;
        __half* sV = sK + 64 * FPITCH_H;
        #pragma unroll
        for (int i = 0; i < 4; i++) {
            int idx = t + 256 * i;
            int row = idx >> 4;
            int c8 = (idx & 15) * 8;
            const __half* kp = QKV + (long long)(kt * 64 + row) * (3 * CC) + CC + head * DH + c8;
            cpa16(sK + row * FPITCH_H + c8, kp, 16);
            cpa16(sV + row * FPITCH_H + c8, kp + CC, 16);
        }
    };

    uint32_t qf[8][4];
    {
        const __half* q0p = QKV + (long long)(qbase + row0) * (3 * CC) + head * DH;
        const __half* q1p = q0p + 8LL * (3 * CC);
        #pragma unroll
        for (int kc = 0; kc < 8; kc++) {
            qf[kc][0] = scale_h2(*(const uint32_t*)(q0p + kc * 16 + 2 * r), scale);
            qf[kc][1] = scale_h2(*(const uint32_t*)(q1p + kc * 16 + 2 * r), scale);
            qf[kc][2] = scale_h2(*(const uint32_t*)(q0p + kc * 16 + 2 * r + 8), scale);
            qf[kc][3] = scale_h2(*(const uint32_t*)(q1p + kc * 16 + 2 * r + 8), scale);
        }
    }

    float oacc[16][4];
    #pragma unroll
    for (int df = 0; df < 16; df++)
        #pragma unroll
        for (int e = 0; e < 4; e++) oacc[df][e] = 0.0f;
    float m0 = -1e30f, m1 = -1e30f, l0 = 0.0f, l1 = 0.0f;

    const int grp = lane >> 3;
    const int lr = lane & 7;

    const int ntiles = n / 64;
    issueKV(0, 0);
    cpa_commit();

    for (int kt = 0; kt < ntiles; kt++) {
        if (kt + 1 < ntiles) {
            issueKV(kt + 1, (kt + 1) & 1);
            cpa_commit();
            cpa_wait1();
        } else {
            cpa_wait0();
        }
        __syncthreads();

        const uint32_t skb = sbase + ((kt & 1) * FL_STAGE_H) * 2;
        const uint32_t svb = skb + 64 * FPITCH_H * 2;

        float sacc[8][4];
        #pragma unroll
        for (int nf = 0; nf < 8; nf++)
            #pragma unroll
            for (int e = 0; e < 4; e++) sacc[nf][e] = 0.0f;
        #pragma unroll
        for (int kc = 0; kc < 8; kc++) {
            #pragma unroll
            for (int nfp = 0; nfp < 4; nfp++) {
                int kvr = nfp * 16 + ((grp & 2) ? 8 : 0) + lr;
                int dc = kc * 16 + ((grp & 1) ? 8 : 0);
                uint32_t b0, b1, b2, b3;
                ldsm_x4(b0, b1, b2, b3, skb + (kvr * FPITCH_H + dc) * 2);
                uint32_t bA[2] = {b0, b1}, bB[2] = {b2, b3};
                mma_f16(sacc[2 * nfp], qf[kc], bA, sacc[2 * nfp]);
                mma_f16(sacc[2 * nfp + 1], qf[kc], bB, sacc[2 * nfp + 1]);
            }
        }

        float tm0 = -1e30f, tm1 = -1e30f;
        #pragma unroll
        for (int nf = 0; nf < 8; nf++) {
            tm0 = fmaxf(tm0, fmaxf(sacc[nf][0], sacc[nf][1]));
            tm1 = fmaxf(tm1, fmaxf(sacc[nf][2], sacc[nf][3]));
        }
        tm0 = fmaxf(tm0, __shfl_xor_sync(0xffffffffu, tm0, 1));
        tm0 = fmaxf(tm0, __shfl_xor_sync(0xffffffffu, tm0, 2));
        tm1 = fmaxf(tm1, __shfl_xor_sync(0xffffffffu, tm1, 1));
        tm1 = fmaxf(tm1, __shfl_xor_sync(0xffffffffu, tm1, 2));
        const float nm0 = fmaxf(m0, tm0);
        const float nm1 = fmaxf(m1, tm1);
        const float cor0 = __expf(m0 - nm0);
        const float cor1 = __expf(m1 - nm1);
        m0 = nm0; m1 = nm1;

        float ts0 = 0.0f, ts1 = 0.0f;
        #pragma unroll
        for (int nf = 0; nf < 8; nf++) {
            sacc[nf][0] = __expf(sacc[nf][0] - m0);
            sacc[nf][1] = __expf(sacc[nf][1] - m0);
            sacc[nf][2] = __expf(sacc[nf][2] - m1);
            sacc[nf][3] = __expf(sacc[nf][3] - m1);
            ts0 += sacc[nf][0] + sacc[nf][1];
            ts1 += sacc[nf][2] + sacc[nf][3];
        }
        ts0 += __shfl_xor_sync(0xffffffffu, ts0, 1);
        ts0 += __shfl_xor_sync(0xffffffffu, ts0, 2);
        ts1 += __shfl_xor_sync(0xffffffffu, ts1, 1);
        ts1 += __shfl_xor_sync(0xffffffffu, ts1, 2);
        l0 = l0 * cor0 + ts0;
        l1 = l1 * cor1 + ts1;

        uint32_t pf[4][4];
        #pragma unroll
        for (int j = 0; j < 4; j++) {
            pf[j][0] = pack_h2(sacc[2 * j][0], sacc[2 * j][1]);
            pf[j][1] = pack_h2(sacc[2 * j][2], sacc[2 * j][3]);
            pf[j][2] = pack_h2(sacc[2 * j + 1][0], sacc[2 * j + 1][1]);
            pf[j][3] = pack_h2(sacc[2 * j + 1][2], sacc[2 * j + 1][3]);
        }

        #pragma unroll
        for (int df = 0; df < 16; df++) {
            oacc[df][0] *= cor0; oacc[df][1] *= cor0;
            oacc[df][2] *= cor1; oacc[df][3] *= cor1;
        }

        #pragma unroll
        for (int j = 0; j < 4; j++) {
            #pragma unroll
            for (int dfp = 0; dfp < 8; dfp++) {
                int kvr = 16 * j + ((grp & 1) ? 8 : 0) + lr;
                int dc = dfp * 16 + ((grp & 2) ? 8 : 0);
                uint32_t b0, b1, b2, b3;
                ldsm_x4_t(b0, b1, b2, b3, svb + (kvr * FPITCH_H + dc) * 2);
                uint32_t bA[2] = {b0, b1}, bB[2] = {b2, b3};
                mma_f16(oacc[2 * dfp], pf[j], bA, oacc[2 * dfp]);
                mma_f16(oacc[2 * dfp + 1], pf[j], bB, oacc[2 * dfp + 1]);
            }
        }
        __syncthreads();
    }

    const float inv0 = 1.0f / l0;
    const float inv1 = 1.0f / l1;
    #pragma unroll
    for (int df = 0; df < 16; df++) {
        const int gc = head * DH + df * 8 + 2 * r;
        *reinterpret_cast<__half2*>(O + (long long)(qbase + row0) * CC + gc) =
            __floats2half2_rn(oacc[df][0] * inv0, oacc[df][1] * inv0);
        *reinterpret_cast<__half2*>(O + (long long)(qbase + row0 + 8) * CC + gc) =
            __floats2half2_rn(oacc[df][2] * inv1, oacc[df][3] * inv1);
    }
}

// ---------------------------------------------------------------------------
// Block reduction (128 threads)
// ---------------------------------------------------------------------------
__device__ __forceinline__ float blockReduceSum128(float v, float* red) {
    #pragma unroll
    for (int o = 16; o > 0; o >>= 1) v += __shfl_xor_sync(0xffffffffu, v, o);
    int w = threadIdx.x >> 5;
    if ((threadIdx.x & 31) == 0) red[w] = v;
    __syncthreads();
    float rr;
    if (threadIdx.x < 32) {
        rr = (threadIdx.x < 4) ? red[threadIdx.x] : 0.0f;
        #pragma unroll
        for (int o = 2; o > 0; o >>= 1) rr += __shfl_xor_sync(0xffffffffu, rr, o);
        if (threadIdx.x == 0) red[0] = rr;
    }
    __syncthreads();
    rr = red[0];
    __syncthreads();
    return rr;
}

// ---------------------------------------------------------------------------
// LN(a+b)*g+beta -> fp32 out + half out. 128 threads, float4-vectorized.
// ---------------------------------------------------------------------------
__global__ void add_ln_kernel(const float* __restrict__ a, const float* __restrict__ b,
                              const float* __restrict__ g, const float* __restrict__ be,
                              float* __restrict__ out, __half* __restrict__ outH)
{
    long long row = blockIdx.x;
    const float4* a4 = (const float4*)(a + row * CC);
    const float4* b4 = (const float4*)(b + row * CC);
    int tid = threadIdx.x;

    float4 av = a4[tid];
    float4 bv = b4[tid];
    float4 x;
    x.x = av.x + bv.x; x.y = av.y + bv.y; x.z = av.z + bv.z; x.w = av.w + bv.w;

    __shared__ float red[4];
    float mu = blockReduceSum128(x.x + x.y + x.z + x.w, red) * (1.0f / CC);
    float dx = x.x - mu, dy = x.y - mu, dz = x.z - mu, dw = x.w - mu;
    float var = blockReduceSum128(dx * dx + dy * dy + dz * dz + dw * dw, red) * (1.0f / CC);
    float rstd = rsqrtf(var + 1e-5f);

    const float4 gv = ((const float4*)g)[tid];
    const float4 bev = ((const float4*)be)[tid];
    float4 y;
    y.x = dx * rstd * gv.x + bev.x;
    y.y = dy * rstd * gv.y + bev.y;
    y.z = dz * rstd * gv.z + bev.z;
    y.w = dw * rstd * gv.w + bev.w;

    ((float4*)(out + row * CC))[tid] = y;
    __half2 h0 = __floats2half2_rn(y.x, y.y);
    __half2 h1 = __floats2half2_rn(y.z, y.w);
    uint2 ho;
    ho.x = *reinterpret_cast<uint32_t*>(&h0);
    ho.y = *reinterpret_cast<uint32_t*>(&h1);
    ((uint2*)(outH + row * CC))[tid] = ho;
}

// ---------------------------------------------------------------------------
// Masked-mean aggregation, vectorized float4 -> half2 out (+ optional coef)
// ---------------------------------------------------------------------------
__global__ void agg_kernel(const float* __restrict__ X, int C,
                           const int* __restrict__ nbm,
                           const float* __restrict__ childMask,
                           __half* __restrict__ out, float* __restrict__ coefOut, int P)
{
    int C4 = C >> 2;
    long long idx = (long long)blockIdx.x * blockDim.x + threadIdx.x;
    if (idx >= (long long)P * C4) return;
    int p = (int)(idx / C4);
    int c4 = (int)(idx % C4);
    const float4* X4 = (const float4*)X;
    float4 sum = make_float4(0.f, 0.f, 0.f, 0.f);
    float den = 0.0f, wsum = 0.0f;
    #pragma unroll
    for (int f = 0; f < FAN; f++) {
        float nb = (float)nbm[p * FAN + f];
        den += nb;
        float w = nb * (childMask ? childMask[p * FAN + f] : 1.0f);
        wsum += w;
        float4 v = X4[(long long)(p * FAN + f) * C4 + c4];
        sum.x += w * v.x; sum.y += w * v.y; sum.z += w * v.z; sum.w += w * v.w;
    }
    den = fmaxf(den, 1.0f);
    float inv = 1.0f / den;
    __half2 a = __floats2half2_rn(sum.x * inv, sum.y * inv);
    __half2 b = __floats2half2_rn(sum.z * inv, sum.w * inv);
    uint2 o;
    o.x = *reinterpret_cast<uint32_t*>(&a);
    o.y = *reinterpret_cast<uint32_t*>(&b);
    ((uint2*)out)[(long long)p * C4 + c4] = o;
    if (coefOut && c4 == 0) coefOut[p] = wsum * inv;
}

// ---------------------------------------------------------------------------
// Multi-segment vectorized fp32 -> fp16 conversion
// ---------------------------------------------------------------------------
#define MAXSEG 12
struct CvtJobs {
    const float* src[MAXSEG];
    __half* dst[MAXSEG];
    int quads[MAXSEG];
    int nseg;
};

__global__ void cvt_multi_kernel(CvtJobs jobs)
{
    int seg = blockIdx.y;
    if (seg >= jobs.nseg) return;
    const float4* src = (const float4*)jobs.src[seg];
    uint2* dst = (uint2*)jobs.dst[seg];
    int nq = jobs.quads[seg];
    for (int i = blockIdx.x * blockDim.x + threadIdx.x; i < nq; i += gridDim.x * blockDim.x) {
        float4 v = src[i];
        __half2 a = __floats2half2_rn(v.x, v.y);
        __half2 b = __floats2half2_rn(v.z, v.w);
        uint2 o;
        o.x = *reinterpret_cast<uint32_t*>(&a);
        o.y = *reinterpret_cast<uint32_t*>(&b);
        dst[i] = o;
    }
}

// ---------------------------------------------------------------------------
// Host orchestration
// ---------------------------------------------------------------------------
static void gemm(cudaStream_t st, int M, int N, int K,
                 const __half* A, int lda, const __half* A2, int kSplit,
                 const __half* B, int ldb,
                 float* C, __half* Ch, int ldc,
                 const float* bias, const float* biasScale, int relu,
                 const float* addC, const float* rowMask)
{
    dim3 grid((N + GBN - 1) / GBN, (M + GBM - 1) / GBM);
    gemm_f16_kernel<<<grid, 256, GEMM_SMEM, st>>>(
        M, N, K, A, lda, A2, kSplit, B, ldb, C, Ch, ldc,
        bias, biasScale, relu, addC, rowMask);
}

struct Scratch {
    float *S1E, *S1N, *S0, *AGGC, *HL, *H1, *ATT, *H2;
    __half *S1Eh, *S0h, *AGGFh, *AGGh, *H1h, *QKVh, *ATTOh, *H2h, *FF1h;
    float *HL0, *H10, *ATT0, *H20;
    __half *H1h0, *QKVh0, *ATTOh0, *H2h0, *FF1h0, *AGGh0;
    __half *embWh, *sageWh, *qkvWh, *outWh, *ffnW1h, *ffnW2h, *clsWh, *feats0h, *feats1h;
};

static Scratch get_scratch() {
    Scratch s; void* p;
    cudaGetSymbolAddress(&p, g_S1E);    s.S1E    = (float*)p;
    cudaGetSymbolAddress(&p, g_S1N);    s.S1N    = (float*)p;
    cudaGetSymbolAddress(&p, g_S0);     s.S0     = (float*)p;
    cudaGetSymbolAddress(&p, g_AGGC);   s.AGGC   = (float*)p;
    cudaGetSymbolAddress(&p, g_HL);     s.HL     = (float*)p;
    cudaGetSymbolAddress(&p, g_H1);     s.H1     = (float*)p;
    cudaGetSymbolAddress(&p, g_ATT);    s.ATT    = (float*)p;
    cudaGetSymbolAddress(&p, g_H2);     s.H2     = (float*)p;
    cudaGetSymbolAddress(&p, g_S1Eh);   s.S1Eh   = (__half*)p;
    cudaGetSymbolAddress(&p, g_S0h);    s.S0h    = (__half*)p;
    cudaGetSymbolAddress(&p, g_AGGFh);  s.AGGFh  = (__half*)p;
    cudaGetSymbolAddress(&p, g_AGGh);   s.AGGh   = (__half*)p;
    cudaGetSymbolAddress(&p, g_H1h);    s.H1h    = (__half*)p;
    cudaGetSymbolAddress(&p, g_QKVh);   s.QKVh   = (__half*)p;
    cudaGetSymbolAddress(&p, g_ATTOh);  s.ATTOh  = (__half*)p;
    cudaGetSymbolAddress(&p, g_H2h);    s.H2h    = (__half*)p;
    cudaGetSymbolAddress(&p, g_FF1h);   s.FF1h   = (__half*)p;
    cudaGetSymbolAddress(&p, g_HL0);    s.HL0    = (float*)p;
    cudaGetSymbolAddress(&p, g_H10);    s.H10    = (float*)p;
    cudaGetSymbolAddress(&p, g_ATT0);   s.ATT0   = (float*)p;
    cudaGetSymbolAddress(&p, g_H20);    s.H20    = (float*)p;
    cudaGetSymbolAddress(&p, g_H1h0);   s.H1h0   = (__half*)p;
    cudaGetSymbolAddress(&p, g_QKVh0);  s.QKVh0  = (__half*)p;
    cudaGetSymbolAddress(&p, g_ATTOh0); s.ATTOh0 = (__half*)p;
    cudaGetSymbolAddress(&p, g_H2h0);   s.H2h0   = (__half*)p;
    cudaGetSymbolAddress(&p, g_FF1h0);  s.FF1h0  = (__half*)p;
    cudaGetSymbolAddress(&p, g_AGGh0);  s.AGGh0  = (__half*)p;
    cudaGetSymbolAddress(&p, g_embWh);  s.embWh  = (__half*)p;
    cudaGetSymbolAddress(&p, g_sageWh); s.sageWh = (__half*)p;
    cudaGetSymbolAddress(&p, g_qkvWh);  s.qkvWh  = (__half*)p;
    cudaGetSymbolAddress(&p, g_outWh);  s.outWh  = (__half*)p;
    cudaGetSymbolAddress(&p, g_ffnW1h); s.ffnW1h = (__half*)p;
    cudaGetSymbolAddress(&p, g_ffnW2h); s.ffnW2h = (__half*)p;
    cudaGetSymbolAddress(&p, g_clsWh);  s.clsWh  = (__half*)p;
    cudaGetSymbolAddress(&p, g_feats0h); s.feats0h = (__half*)p;
    cudaGetSymbolAddress(&p, g_feats1h); s.feats1h = (__half*)p;
    return s;
}

struct LayerW {
    const __half *sageW, *qkvW, *outW, *ffnW1, *ffnW2;
    const float *sageB, *qkvB, *outB, *ffnB1, *ffnB2;
    const float *n1g, *n1b, *n2g, *n2b;
};

struct BlockScr {
    float *HL, *H1, *ATT, *H2;
    __half *H1h, *QKVh, *ATTOh, *H2h, *FF1h;
};

static void block_forward(cudaStream_t st, int n,
                          const float* sf, const __half* sfh, const __half* agg,
                          float* outState, __half* outStateH,
                          const float* rowMask, const LayerW& w, const BlockScr& b)
{
    gemm(st, n, CC, 2 * CC, sfh, CC, agg, CC, w.sageW, 2 * CC,
         b.HL, nullptr, CC, w.sageB, nullptr, 0, nullptr, nullptr);
    add_ln_kernel<<<n, 128, 0, st>>>(sf, b.HL, w.n1g, w.n1b, b.H1, b.H1h);

    gemm(st, n, 3 * CC, CC, b.H1h, CC, nullptr, CC, w.qkvW, CC,
         nullptr, b.QKVh, 3 * CC, w.qkvB, nullptr, 0, nullptr, nullptr);

    {
        dim3 grid(n / 128, HH);
        flash_f16_kernel<<<grid, 256, FLASH_SMEM, st>>>(b.QKVh, b.ATTOh, n);
    }

    gemm(st, n, CC, CC, b.ATTOh, CC, nullptr, CC, w.outW, CC,
         b.ATT, nullptr, CC, w.outB, nullptr, 0, nullptr, nullptr);
    add_ln_kernel<<<n, 128, 0, st>>>(b.H1, b.ATT, w.n2g, w.n2b, b.H2, b.H2h);

    gemm(st, n, 2 * CC, CC, b.H2h, CC, nullptr, CC, w.ffnW1, CC,
         nullptr, b.FF1h, 2 * CC, w.ffnB1, nullptr, 1, nullptr, nullptr);
    gemm(st, n, CC, 2 * CC, b.FF1h, 2 * CC, nullptr, 2 * CC, w.ffnW2, 2 * CC,
         outState, outStateH, CC, w.ffnB2, nullptr, 0, b.H2, rowMask);
}

extern "C" void kernel_launch(void* const* d_in, const int* in_sizes, int n_in,
                              void* d_out, int out_size)
{
    const float* feats0  = (const float*)d_in[0];
    const float* feats1  = (const float*)d_in[1];
    const float* feats2  = (const float*)d_in[2];
    const float* nmask0  = (const float*)d_in[3];
    const float* nmask1  = (const float*)d_in[4];
    const float* nmask2  = (const float*)d_in[5];
    const int*   nbmask0 = (const int*)d_in[6];
    const int*   nbmask1 = (const int*)d_in[7];
    const float* emb_w   = (const float*)d_in[8];
    const float* emb_b   = (const float*)d_in[9];
    const float* sage_w  = (const float*)d_in[10];
    const float* sage_b  = (const float*)d_in[11];
    const float* qkv_w   = (const float*)d_in[12];
    const float* qkv_b   = (const float*)d_in[13];
    const float* out_w   = (const float*)d_in[14];
    const float* out_b   = (const float*)d_in[15];
    const float* n1_g    = (const float*)d_in[16];
    const float* n1_b    = (const float*)d_in[17];
    const float* n2_g    = (const float*)d_in[18];
    const float* n2_b    = (const float*)d_in[19];
    const float* ffn_w1  = (const float*)d_in[20];
    const float* ffn_b1  = (const float*)d_in[21];
    const float* ffn_w2  = (const float*)d_in[22];
    const float* ffn_b2  = (const float*)d_in[23];
    const float* cls_w   = (const float*)d_in[24];
    const float* cls_b   = (const float*)d_in[25];
    float* out = (float*)d_out;

    cudaFuncSetAttribute(gemm_f16_kernel, cudaFuncAttributeMaxDynamicSharedMemorySize,
                         GEMM_SMEM);
    cudaFuncSetAttribute(flash_f16_kernel, cudaFuncAttributeMaxDynamicSharedMemorySize,
                         FLASH_SMEM);

    Scratch s = get_scratch();

    // second stream + events for concurrent small block (created per call; the
    // harness invokes kernel_launch only a few times, so handles are not leaked
    // at scale and no device-memory allocation is involved)
    cudaStream_t sB;
    cudaStreamCreateWithFlags(&sB, cudaStreamNonBlocking);
    cudaEvent_t evFork, evJoin;
    cudaEventCreateWithFlags(&evFork, cudaEventDisableTiming);
    cudaEventCreateWithFlags(&evJoin, cudaEventDisableTiming);

    // ---- all fp32->fp16 conversions in one vectorized launch (main stream) ----
    {
        CvtJobs j;
        j.src[0] = emb_w;   j.dst[0] = s.embWh;   j.quads[0] = CC * INDIM / 4;
        j.src[1] = sage_w;  j.dst[1] = s.sageWh;  j.quads[1] = NL * CC * 2 * CC / 4;
        j.src[2] = qkv_w;   j.dst[2] = s.qkvWh;   j.quads[2] = NL * 3 * CC * CC / 4;
        j.src[3] = out_w;   j.dst[3] = s.outWh;   j.quads[3] = NL * CC * CC / 4;
        j.src[4] = ffn_w1;  j.dst[4] = s.ffnW1h;  j.quads[4] = NL * 2 * CC * CC / 4;
        j.src[5] = ffn_w2;  j.dst[5] = s.ffnW2h;  j.quads[5] = NL * CC * 2 * CC / 4;
        j.src[6] = cls_w;   j.dst[6] = s.clsWh;   j.quads[6] = NC * CC / 4;
        j.src[7] = feats0;  j.dst[7] = s.feats0h; j.quads[7] = N0 * INDIM / 4;
        j.src[8] = feats1;  j.dst[8] = s.feats1h; j.quads[8] = N1 * INDIM / 4;
        j.nseg = 9;
        for (int i = j.nseg; i < MAXSEG; i++) { j.src[i] = nullptr; j.dst[i] = nullptr; j.quads[i] = 0; }
        dim3 grid(128, j.nseg);
        cvt_multi_kernel<<<grid, 256>>>(j);
    }

    LayerW w[NL];
    for (int li = 0; li < NL; li++) {
        w[li].sageW = s.sageWh + (long long)li * CC * 2 * CC;
        w[li].qkvW  = s.qkvWh  + (long long)li * 3 * CC * CC;
        w[li].outW  = s.outWh  + (long long)li * CC * CC;
        w[li].ffnW1 = s.ffnW1h + (long long)li * 2 * CC * CC;
        w[li].ffnW2 = s.ffnW2h + (long long)li * CC * 2 * CC;
        w[li].sageB = sage_b + li * CC;
        w[li].qkvB  = qkv_b  + li * 3 * CC;
        w[li].outB  = out_b  + li * CC;
        w[li].ffnB1 = ffn_b1 + li * 2 * CC;
        w[li].ffnB2 = ffn_b2 + li * CC;
        w[li].n1g = n1_g + li * CC;  w[li].n1b = n1_b + li * CC;
        w[li].n2g = n2_g + li * CC;  w[li].n2b = n2_b + li * CC;
    }

    BlockScr big   = { s.HL,  s.H1,  s.ATT,  s.H2,
                       s.H1h, s.QKVh, s.ATTOh, s.H2h, s.FF1h };
    BlockScr small = { s.HL0, s.H10, s.ATT0, s.H20,
                       s.H1h0, s.QKVh0, s.ATTOh0, s.H2h0, s.FF1h0 };

    // ---- depth-1 embedding (needed by BOTH streams), main stream ----
    gemm(0, N1, CC, INDIM, s.feats1h, INDIM, nullptr, INDIM, s.embWh, INDIM,
         s.S1E, s.S1Eh, CC, emb_b, nullptr, 0, nullptr, nmask1);

    // ---- fork: stream B computes S0 embed + layer-0 depth-0 block (uses
    //      PRE-layer S1E), fully concurrent with the big N1 block ----
    cudaEventRecord(evFork, 0);
    cudaStreamWaitEvent(sB, evFork, 0);

    gemm(sB, N0, CC, INDIM, s.feats0h, INDIM, nullptr, INDIM, s.embWh, INDIM,
         s.S0, s.S0h, CC, emb_b, nullptr, 0, nullptr, nmask0);
    agg_kernel<<<(int)(((long long)N0 * CC / 4 + 255) / 256), 256, 0, sB>>>(
        s.S1E, CC, nbmask0, nullptr, s.AGGh0, nullptr, N0);
    block_forward(sB, N0, s.S0, s.S0h, s.AGGh0, s.S0, s.S0h, nmask0, w[0], small);
    cudaEventRecord(evJoin, sB);

    // ---- main stream: depth-2 agg + AGG embed + layer-0 depth-1 (n=4096) ----
    agg_kernel<<<(int)(((long long)N1 * INDIM / 4 + 255) / 256), 256>>>(
        feats2, INDIM, nbmask1, nmask2, s.AGGFh, s.AGGC, N1);
    gemm(0, N1, CC, INDIM, s.AGGFh, INDIM, nullptr, INDIM, s.embWh, INDIM,
         nullptr, s.AGGh, CC, emb_b, s.AGGC, 0, nullptr, nullptr);
    block_forward(0, N1, s.S1E, s.S1Eh, s.AGGh, s.S1N, nullptr, nmask1, w[0], big);

    // ---- join, then layer 1 depth 0 (needs S1N + S0') ----
    cudaStreamWaitEvent(0, evJoin, 0);
    agg_kernel<<<(int)(((long long)N0 * CC / 4 + 255) / 256), 256>>>(
        s.S1N, CC, nbmask0, nullptr, s.AGGh0, nullptr, N0);
    block_forward(0, N0, s.S0, s.S0h, s.AGGh0, s.S0, s.S0h, nmask0, w[1], small);

    // ---- classifier ----
    gemm(0, N0, NC, CC, s.S0h, CC, nullptr, CC, s.clsWh, CC,
         out, nullptr, NC, cls_b, nullptr, 0, nullptr, nullptr);
}